// round 7
// baseline (speedup 1.0000x reference)
#include <cuda_runtime.h>
#include <math.h>
#include <stdint.h>

// ---------------- problem constants ----------------
#define TOKENS 200704          // 8*8*56*56
#define CD     128
#define NWIN   2048
#define NL     98
#define NHEAD  4

#define GEMM_SMEM_DB (4 * 16384)    // 64KB qkv/proj gemm
#define MLP_SMEM     (10 * 16384)   // 160KB: Ys[4] + Hs[4] + Ws[2] chunks of [128][32]

// weight cvt offsets (floats)
#define W_QKV  0
#define W_PROJ 49152
#define W_FC1  65536
#define W_FC2  131072
#define W_TOT  196608

// ---------------- scratch ----------------
__device__ float g_xw  [(size_t)TOKENS * CD];
__device__ float g_qkv [(size_t)TOKENS * 3 * CD];
__device__ float g_bias[(size_t)NHEAD * NL * NL];
__device__ float g_attn[(size_t)TOKENS * CD];
__device__ float g_x2  [(size_t)TOKENS * CD];
__device__ float g_y   [(size_t)TOKENS * CD];
__device__ float g_wcvt[W_TOT];

// ---------------- helpers ----------------
__device__ __forceinline__ float tf32r(float v) {
    uint32_t o;
    asm("cvt.rna.tf32.f32 %0, %1;" : "=r"(o) : "f"(v));
    return __uint_as_float(o);
}
__device__ __forceinline__ void mma_tf32(float c[4],
                                         uint32_t a0, uint32_t a1, uint32_t a2, uint32_t a3,
                                         uint32_t b0, uint32_t b1) {
    asm volatile(
        "mma.sync.aligned.m16n8k8.row.col.f32.tf32.tf32.f32 "
        "{%0,%1,%2,%3}, {%4,%5,%6,%7}, {%8,%9}, {%0,%1,%2,%3};\n"
        : "+f"(c[0]), "+f"(c[1]), "+f"(c[2]), "+f"(c[3])
        : "r"(a0), "r"(a1), "r"(a2), "r"(a3), "r"(b0), "r"(b1));
}
__device__ __forceinline__ uint32_t smem_u32(const void* p) {
    uint32_t a;
    asm("{ .reg .u64 t; cvta.to.shared.u64 t, %1; cvt.u32.u64 %0, t; }" : "=r"(a) : "l"(p));
    return a;
}
#define CP16(dst, src) \
    asm volatile("cp.async.cg.shared.global [%0], [%1], 16;\n" :: "r"(dst), "l"(src))
#define CP_COMMIT() asm volatile("cp.async.commit_group;\n" ::: "memory")
#define CP_WAIT(n)  asm volatile("cp.async.wait_group %0;\n" :: "n"(n) : "memory")

// one 128x128x32 mma sub-block: A chunk [128][32] swz, B chunk [128][32] swz
__device__ __forceinline__ void mma_chunk(const float* __restrict__ Ab,
                                          const float* __restrict__ Bb,
                                          float (*acc)[4][4],
                                          int wm, int wn, int g, int cc) {
    #pragma unroll
    for (int ks = 0; ks < 4; ks++) {
        int k0 = ks * 8;
        int sw = g * 4;
        uint32_t af[4][4];
        #pragma unroll
        for (int mt = 0; mt < 4; mt++) {
            int rb = wm * 64 + mt * 16 + g;
            af[mt][0] = __float_as_uint(Ab[rb * 32       + ((k0 + cc)     ^ sw)]);
            af[mt][1] = __float_as_uint(Ab[(rb + 8) * 32 + ((k0 + cc)     ^ sw)]);
            af[mt][2] = __float_as_uint(Ab[rb * 32       + ((k0 + cc + 4) ^ sw)]);
            af[mt][3] = __float_as_uint(Ab[(rb + 8) * 32 + ((k0 + cc + 4) ^ sw)]);
        }
        uint32_t bf[4][2];
        #pragma unroll
        for (int nt = 0; nt < 4; nt++) {
            int nb = wn * 32 + nt * 8 + g;
            bf[nt][0] = __float_as_uint(Bb[nb * 32 + ((k0 + cc)     ^ sw)]);
            bf[nt][1] = __float_as_uint(Bb[nb * 32 + ((k0 + cc + 4) ^ sw)]);
        }
        #pragma unroll
        for (int mt = 0; mt < 4; mt++)
            #pragma unroll
            for (int nt = 0; nt < 4; nt++)
                mma_tf32(acc[mt][nt], af[mt][0], af[mt][1], af[mt][2], af[mt][3],
                         bf[nt][0], bf[nt][1]);
    }
}

// window row -> spatial token (same mapping as ln1 gather)
__device__ __forceinline__ int win_to_spatial(int gr) {
    int win = gr / NL, n = gr % NL;
    int bb = win >> 8, wl = win & 255;
    int dz = wl >> 6, hy = (wl >> 3) & 7, wx = wl & 7;
    int id = n / 49, ih = (n / 7) % 7, iw = n % 7;
    int d  = (dz * 2 + id + 1) & 7;
    int hh = hy * 7 + ih + 3; if (hh >= 56) hh -= 56;
    int ww = wx * 7 + iw + 3; if (ww >= 56) ww -= 56;
    return ((bb * 8 + d) * 56 + hh) * 56 + ww;
}

// ---------------- weight tf32 pre-conversion ----------------
__global__ void cvt_kernel(const float* __restrict__ in, float* __restrict__ out, int n) {
    int i = blockIdx.x * 256 + threadIdx.x;
    if (i < n) out[i] = tf32r(in[i]);
}

// ============ QKV GEMM (double-buffered cp.async, bias epilogue) ============
__global__ void __launch_bounds__(256, 2)
qkv_gemm(const float* __restrict__ A, const float* __restrict__ W,
         const float* __restrict__ bias, float* __restrict__ C, int K, int N) {
    extern __shared__ float gsm[];
    uint32_t sb = smem_u32(gsm);
    int tid = threadIdx.x;
    int wid = tid >> 5, lane = tid & 31;
    int g = lane >> 2, cc = lane & 3;
    int m0 = blockIdx.y * 128, n0 = blockIdx.x * 128;
    int wm = wid & 1, wn = wid >> 1;

    float acc[4][4][4];
    #pragma unroll
    for (int i = 0; i < 4; i++)
        #pragma unroll
        for (int j = 0; j < 4; j++)
            #pragma unroll
            for (int t = 0; t < 4; t++) acc[i][j][t] = 0.0f;

    int r_ld = tid >> 3, c4_ld = tid & 7;
    uint32_t soff_base = ((uint32_t)r_ld * 32 + (((uint32_t)c4_ld * 4) ^ ((r_ld & 7) * 4))) * 4;

    int nc = K >> 5;
    auto issue = [&](int kc, int buf) {
        int k0 = kc * 32;
        #pragma unroll
        for (int i = 0; i < 4; i++) {
            int r = r_ld + i * 32;
            uint32_t soff = soff_base + (uint32_t)i * 4096;
            CP16(sb + buf * 16384 + soff, A + (size_t)(m0 + r) * K + k0 + c4_ld * 4);
            CP16(sb + 32768 + buf * 16384 + soff, W + (size_t)(n0 + r) * K + k0 + c4_ld * 4);
        }
        CP_COMMIT();
    };

    issue(0, 0);
    for (int kc = 0; kc < nc; kc++) {
        if (kc + 1 < nc) { issue(kc + 1, (kc + 1) & 1); CP_WAIT(1); }
        else             { CP_WAIT(0); }
        __syncthreads();
        mma_chunk(gsm + (kc & 1) * 4096, gsm + 8192 + (kc & 1) * 4096, acc, wm, wn, g, cc);
        __syncthreads();
    }

    #pragma unroll
    for (int mt = 0; mt < 4; mt++) {
        int r0 = m0 + wm * 64 + mt * 16 + g;
        #pragma unroll
        for (int nt = 0; nt < 4; nt++) {
            int cb = n0 + wn * 32 + nt * 8 + cc * 2;
            float2 bb = *reinterpret_cast<const float2*>(bias + cb);
            #pragma unroll
            for (int hrow = 0; hrow < 2; hrow++) {
                int row = r0 + hrow * 8;
                float2 o;
                o.x = acc[mt][nt][hrow * 2 + 0] + bb.x;
                o.y = acc[mt][nt][hrow * 2 + 1] + bb.y;
                *reinterpret_cast<float2*>(C + (size_t)row * N + cb) = o;
            }
        }
    }
}

// ============ proj GEMM + residual + LN2 fused epilogue =====================
__global__ void __launch_bounds__(256, 2)
proj_gemm(const float* __restrict__ A, const float* __restrict__ W,
          const float* __restrict__ bias, const float* __restrict__ x,
          const float* __restrict__ n2g, const float* __restrict__ n2b) {
    extern __shared__ float gsm[];
    __shared__ float rs1[128];
    __shared__ float rs2[128];
    uint32_t sb = smem_u32(gsm);
    int tid = threadIdx.x;
    int wid = tid >> 5, lane = tid & 31;
    int g = lane >> 2, cc = lane & 3;
    int m0 = blockIdx.x * 128;
    int wm = wid & 1, wn = wid >> 1;

    float acc[4][4][4];
    #pragma unroll
    for (int i = 0; i < 4; i++)
        #pragma unroll
        for (int j = 0; j < 4; j++)
            #pragma unroll
            for (int t = 0; t < 4; t++) acc[i][j][t] = 0.0f;

    int r_ld = tid >> 3, c4_ld = tid & 7;
    uint32_t soff_base = ((uint32_t)r_ld * 32 + (((uint32_t)c4_ld * 4) ^ ((r_ld & 7) * 4))) * 4;

    auto issue = [&](int kc, int buf) {
        int k0 = kc * 32;
        #pragma unroll
        for (int i = 0; i < 4; i++) {
            int r = r_ld + i * 32;
            uint32_t soff = soff_base + (uint32_t)i * 4096;
            CP16(sb + buf * 16384 + soff, A + (size_t)(m0 + r) * 128 + k0 + c4_ld * 4);
            CP16(sb + 32768 + buf * 16384 + soff, W + (size_t)r * 128 + k0 + c4_ld * 4);
        }
        CP_COMMIT();
    };

    if (tid < 128) { rs1[tid] = 0.0f; rs2[tid] = 0.0f; }

    issue(0, 0);
    for (int kc = 0; kc < 4; kc++) {
        if (kc + 1 < 4) { issue(kc + 1, (kc + 1) & 1); CP_WAIT(1); }
        else            { CP_WAIT(0); }
        __syncthreads();
        mma_chunk(gsm + (kc & 1) * 4096, gsm + 8192 + (kc & 1) * 4096, acc, wm, wn, g, cc);
        __syncthreads();
    }

    // spatial indices for this thread's 8 rows
    int tsp[4][2];
    #pragma unroll
    for (int mt = 0; mt < 4; mt++) {
        int rl = wm * 64 + mt * 16 + g;
        tsp[mt][0] = win_to_spatial(m0 + rl);
        tsp[mt][1] = win_to_spatial(m0 + rl + 8);
    }

    // v2 = acc + bias + x_residual; accumulate row sums
    #pragma unroll
    for (int mt = 0; mt < 4; mt++) {
        #pragma unroll
        for (int hrow = 0; hrow < 2; hrow++) {
            int rl = wm * 64 + mt * 16 + g + hrow * 8;
            float s1 = 0.0f, s2 = 0.0f;
            #pragma unroll
            for (int nt = 0; nt < 4; nt++) {
                int cb = wn * 32 + nt * 8 + cc * 2;
                float2 bb = *reinterpret_cast<const float2*>(bias + cb);
                float2 xv = *reinterpret_cast<const float2*>(x + (size_t)tsp[mt][hrow] * CD + cb);
                float v0 = acc[mt][nt][hrow * 2 + 0] + bb.x + xv.x;
                float v1 = acc[mt][nt][hrow * 2 + 1] + bb.y + xv.y;
                acc[mt][nt][hrow * 2 + 0] = v0;
                acc[mt][nt][hrow * 2 + 1] = v1;
                s1 += v0 + v1;
                s2 += v0 * v0 + v1 * v1;
            }
            atomicAdd(&rs1[rl], s1);
            atomicAdd(&rs2[rl], s2);
        }
    }
    __syncthreads();

    // LN2 + scatter writes
    #pragma unroll
    for (int mt = 0; mt < 4; mt++) {
        #pragma unroll
        for (int hrow = 0; hrow < 2; hrow++) {
            int rl = wm * 64 + mt * 16 + g + hrow * 8;
            int t_sp = tsp[mt][hrow];
            float mean = rs1[rl] * (1.0f / 128.0f);
            float var  = rs2[rl] * (1.0f / 128.0f) - mean * mean;
            float inv  = rsqrtf(var + 1e-5f);
            #pragma unroll
            for (int nt = 0; nt < 4; nt++) {
                int cb = wn * 32 + nt * 8 + cc * 2;
                float v0 = acc[mt][nt][hrow * 2 + 0];
                float v1 = acc[mt][nt][hrow * 2 + 1];
                float2 gg = *reinterpret_cast<const float2*>(n2g + cb);
                float2 bv = *reinterpret_cast<const float2*>(n2b + cb);
                float2 x2o; x2o.x = v0; x2o.y = v1;
                *reinterpret_cast<float2*>(g_x2 + (size_t)t_sp * CD + cb) = x2o;
                float2 yo;
                yo.x = tf32r((v0 - mean) * inv * gg.x + bv.x);
                yo.y = tf32r((v1 - mean) * inv * gg.y + bv.y);
                *reinterpret_cast<float2*>(g_y + (size_t)t_sp * CD + cb) = yo;
            }
        }
    }
}

// ============ fused MLP: out = x2 + fc2(gelu(fc1(y))) ======================
// smem: Ys[4][128][32] | Hs[4][128][32] | Ws[2][128][32]
__global__ void __launch_bounds__(256, 1)
mlp_kernel(const float* __restrict__ w1, const float* __restrict__ b1,
           const float* __restrict__ w2, const float* __restrict__ b2,
           float* __restrict__ out) {
    extern __shared__ float gsm[];
    float* Ys = gsm;                 // 4 chunks
    float* Hs = gsm + 16384;         // 4 chunks
    float* Ws = gsm + 32768;         // 2 buffers
    uint32_t sb = smem_u32(gsm);
    const uint32_t WS_OFF = 32768u * 4u;
    int tid = threadIdx.x;
    int wid = tid >> 5, lane = tid & 31;
    int g = lane >> 2, cc = lane & 3;
    int m0 = blockIdx.x * 128;
    int wm = wid & 1, wn = wid >> 1;

    int r_ld = tid >> 3, c4_ld = tid & 7;
    uint32_t soff_base = ((uint32_t)r_ld * 32 + (((uint32_t)c4_ld * 4) ^ ((r_ld & 7) * 4))) * 4;

    // load full Y tile (4 chunks) as one group
    #pragma unroll
    for (int c = 0; c < 4; c++) {
        #pragma unroll
        for (int i = 0; i < 4; i++) {
            int r = r_ld + i * 32;
            uint32_t soff = soff_base + (uint32_t)i * 4096;
            CP16(sb + (uint32_t)c * 16384 + soff,
                 g_y + (size_t)(m0 + r) * 128 + c * 32 + c4_ld * 4);
        }
    }
    CP_COMMIT();

    auto issueW = [&](const float* W, int rowbase, int colbase, int ldw, int kc, int buf) {
        int k0 = colbase + kc * 32;
        #pragma unroll
        for (int i = 0; i < 4; i++) {
            int r = r_ld + i * 32;
            uint32_t soff = soff_base + (uint32_t)i * 4096;
            CP16(sb + WS_OFF + (uint32_t)buf * 16384 + soff,
                 W + (size_t)(rowbase + r) * ldw + k0 + c4_ld * 4);
        }
        CP_COMMIT();
    };

    float oacc[4][4][4];
    #pragma unroll
    for (int i = 0; i < 4; i++)
        #pragma unroll
        for (int j = 0; j < 4; j++)
            #pragma unroll
            for (int t = 0; t < 4; t++) oacc[i][j][t] = 0.0f;

    for (int hc = 0; hc < 4; hc++) {
        // ---- fc1: H = Y @ W1c^T ----
        float hacc[4][4][4];
        #pragma unroll
        for (int i = 0; i < 4; i++)
            #pragma unroll
            for (int j = 0; j < 4; j++)
                #pragma unroll
                for (int t = 0; t < 4; t++) hacc[i][j][t] = 0.0f;

        issueW(w1, hc * 128, 0, 128, 0, 0);
        for (int kc = 0; kc < 4; kc++) {
            if (kc + 1 < 4) { issueW(w1, hc * 128, 0, 128, kc + 1, (kc + 1) & 1); CP_WAIT(1); }
            else            { CP_WAIT(0); }
            __syncthreads();
            mma_chunk(Ys + kc * 4096, Ws + (kc & 1) * 4096, hacc, wm, wn, g, cc);
            __syncthreads();
        }

        // bias + gelu + tf32, store to Hs (swizzled)
        #pragma unroll
        for (int mt = 0; mt < 4; mt++) {
            #pragma unroll
            for (int hrow = 0; hrow < 2; hrow++) {
                int rl = wm * 64 + mt * 16 + g + hrow * 8;
                #pragma unroll
                for (int nt = 0; nt < 4; nt++) {
                    int cl = wn * 32 + nt * 8 + cc * 2;
                    float2 bb = *reinterpret_cast<const float2*>(b1 + hc * 128 + cl);
                    float v0 = hacc[mt][nt][hrow * 2 + 0] + bb.x;
                    float v1 = hacc[mt][nt][hrow * 2 + 1] + bb.y;
                    v0 = tf32r(0.5f * v0 * (1.0f + erff(v0 * 0.70710678118654752f)));
                    v1 = tf32r(0.5f * v1 * (1.0f + erff(v1 * 0.70710678118654752f)));
                    int c32 = cl & 31;
                    int scol = c32 ^ ((rl & 7) * 4);
                    float2 hv; hv.x = v0; hv.y = v1;
                    *reinterpret_cast<float2*>(Hs + wn * 4096 + rl * 32 + scol) = hv;
                }
            }
        }
        __syncthreads();

        // ---- fc2: out += H @ W2c^T ----
        issueW(w2, 0, hc * 128, 512, 0, 0);
        for (int kc = 0; kc < 4; kc++) {
            if (kc + 1 < 4) { issueW(w2, 0, hc * 128, 512, kc + 1, (kc + 1) & 1); CP_WAIT(1); }
            else            { CP_WAIT(0); }
            __syncthreads();
            mma_chunk(Hs + kc * 4096, Ws + (kc & 1) * 4096, oacc, wm, wn, g, cc);
            __syncthreads();
        }
    }

    // final epilogue: + fc2 bias + x2 residual -> out
    #pragma unroll
    for (int mt = 0; mt < 4; mt++) {
        #pragma unroll
        for (int hrow = 0; hrow < 2; hrow++) {
            int row = m0 + wm * 64 + mt * 16 + g + hrow * 8;
            #pragma unroll
            for (int nt = 0; nt < 4; nt++) {
                int cb = wn * 32 + nt * 8 + cc * 2;
                float2 bb = *reinterpret_cast<const float2*>(b2 + cb);
                float2 r2 = *reinterpret_cast<const float2*>(g_x2 + (size_t)row * CD + cb);
                float2 o;
                o.x = oacc[mt][nt][hrow * 2 + 0] + bb.x + r2.x;
                o.y = oacc[mt][nt][hrow * 2 + 1] + bb.y + r2.y;
                *reinterpret_cast<float2*>(out + (size_t)row * CD + cb) = o;
            }
        }
    }
}

// ---------------- rel-pos bias materialization ----------------
__global__ void bias_kernel(const float* __restrict__ rel_bias) {
    int t = blockIdx.x * blockDim.x + threadIdx.x;
    if (t >= NHEAD * NL * NL) return;
    int h = t / (NL * NL);
    int r = t % (NL * NL);
    int n = r / NL, m = r % NL;
    int id = n / 49, ih = (n / 7) % 7, iw = n % 7;
    int jd = m / 49, jh = (m / 7) % 7, jw = m % 7;
    int ridx = (id - jd + 1) * 169 + (ih - jh + 6) * 13 + (iw - jw + 6);
    g_bias[t] = rel_bias[ridx * NHEAD + h];
}

// ---------------- LN1 + shift + window partition (tf32 out) ----------------
__global__ void ln1_kernel(const float* __restrict__ x,
                           const float* __restrict__ g, const float* __restrict__ b) {
    int warp = blockIdx.x * 8 + (threadIdx.x >> 5);
    int lane = threadIdx.x & 31;
    if (warp >= TOKENS) return;
    int src = win_to_spatial(warp);
    float4 v = reinterpret_cast<const float4*>(x + (size_t)src * CD)[lane];
    float s1 = v.x + v.y + v.z + v.w;
    float s2 = v.x*v.x + v.y*v.y + v.z*v.z + v.w*v.w;
    #pragma unroll
    for (int o = 16; o; o >>= 1) {
        s1 += __shfl_xor_sync(0xffffffffu, s1, o);
        s2 += __shfl_xor_sync(0xffffffffu, s2, o);
    }
    float mean = s1 * (1.0f / 128.0f);
    float var  = s2 * (1.0f / 128.0f) - mean * mean;
    float inv  = rsqrtf(var + 1e-5f);
    float4 gg = reinterpret_cast<const float4*>(g)[lane];
    float4 bv = reinterpret_cast<const float4*>(b)[lane];
    float4 o;
    o.x = tf32r((v.x - mean) * inv * gg.x + bv.x);
    o.y = tf32r((v.y - mean) * inv * gg.y + bv.y);
    o.z = tf32r((v.z - mean) * inv * gg.z + bv.z);
    o.w = tf32r((v.w - mean) * inv * gg.w + bv.w);
    reinterpret_cast<float4*>(g_xw)[(size_t)warp * 32 + lane] = o;
}

// ---------------- flash-style register attention ----------------
__global__ void __launch_bounds__(224, 2)
attn_flash(const float* __restrict__ mask) {
    __shared__ float Qs[112 * 32];
    __shared__ float Ks[104 * 32];
    __shared__ float Vs[104 * 32];
    int win = blockIdx.x, h = blockIdx.y;
    int tid = threadIdx.x, wid = tid >> 5, lane = tid & 31;
    int g = lane >> 2, cc = lane & 3;

    for (int i = tid; i < 14 * 32; i += 224) Qs[98 * 32 + i] = 0.0f;
    if (tid < 192) { Ks[98 * 32 + tid] = 0.0f; Vs[98 * 32 + tid] = 0.0f; }
    const float* base = g_qkv + (size_t)win * NL * 384 + h * 32;
    for (int e = tid; e < 98 * 24; e += 224) {
        int tok = e / 24, p = e - tok * 24;
        int which = p >> 3, c4 = p & 7;
        float4 v = *reinterpret_cast<const float4*>(base + (size_t)tok * 384 + which * 128 + c4 * 4);
        if (which == 0) {
            const float sc = 0.17677669529663689f;
            v.x *= sc; v.y *= sc; v.z *= sc; v.w *= sc;
        }
        float4 t;
        t.x = tf32r(v.x); t.y = tf32r(v.y); t.z = tf32r(v.z); t.w = tf32r(v.w);
        int col = (c4 * 4) ^ ((tok & 7) * 4);
        float* dst = (which == 0 ? Qs : which == 1 ? Ks : Vs) + tok * 32 + col;
        *reinterpret_cast<float4*>(dst) = t;
    }
    __syncthreads();

    int m0 = wid * 16;
    int r0 = m0 + g, r1 = m0 + g + 8;
    int sw = g * 4;

    uint32_t aq[4][4];
    #pragma unroll
    for (int kc = 0; kc < 4; kc++) {
        int col0 = (kc * 8 + cc) ^ sw;
        int col1 = (kc * 8 + cc + 4) ^ sw;
        aq[kc][0] = __float_as_uint(Qs[r0 * 32 + col0]);
        aq[kc][1] = __float_as_uint(Qs[r1 * 32 + col0]);
        aq[kc][2] = __float_as_uint(Qs[r0 * 32 + col1]);
        aq[kc][3] = __float_as_uint(Qs[r1 * 32 + col1]);
    }

    float sacc[13][4];
    #pragma unroll
    for (int nt = 0; nt < 13; nt++) {
        float s[4] = {0.f, 0.f, 0.f, 0.f};
        int nr = nt * 8 + g;
        #pragma unroll
        for (int kc = 0; kc < 4; kc++) {
            int col0 = (kc * 8 + cc) ^ sw;
            int col1 = (kc * 8 + cc + 4) ^ sw;
            uint32_t b0 = __float_as_uint(Ks[nr * 32 + col0]);
            uint32_t b1 = __float_as_uint(Ks[nr * 32 + col1]);
            mma_tf32(s, aq[kc][0], aq[kc][1], aq[kc][2], aq[kc][3], b0, b1);
        }
        sacc[nt][0] = s[0]; sacc[nt][1] = s[1]; sacc[nt][2] = s[2]; sacc[nt][3] = s[3];
    }

    {
        const float* bm = g_bias + (size_t)h * (NL * NL);
        const float* mk = mask + (size_t)(win & 255) * (NL * NL);
        int rc0 = (r0 < 98 ? r0 : 97) * 98;
        int rc1 = (r1 < 98 ? r1 : 97) * 98;
        #pragma unroll
        for (int nt = 0; nt < 13; nt++) {
            int col = nt * 8 + 2 * cc;
            if (col < 98) {
                sacc[nt][0] += __ldg(bm + rc0 + col) + __ldg(mk + rc0 + col);
                sacc[nt][2] += __ldg(bm + rc1 + col) + __ldg(mk + rc1 + col);
            } else { sacc[nt][0] = -1.0e38f; sacc[nt][2] = -1.0e38f; }
            if (col + 1 < 98) {
                sacc[nt][1] += __ldg(bm + rc0 + col + 1) + __ldg(mk + rc0 + col + 1);
                sacc[nt][3] += __ldg(bm + rc1 + col + 1) + __ldg(mk + rc1 + col + 1);
            } else { sacc[nt][1] = -1.0e38f; sacc[nt][3] = -1.0e38f; }
        }
    }

    float mx0 = -1.0e38f, mx1 = -1.0e38f;
    #pragma unroll
    for (int nt = 0; nt < 13; nt++) {
        mx0 = fmaxf(mx0, fmaxf(sacc[nt][0], sacc[nt][1]));
        mx1 = fmaxf(mx1, fmaxf(sacc[nt][2], sacc[nt][3]));
    }
    mx0 = fmaxf(mx0, __shfl_xor_sync(0xffffffffu, mx0, 1));
    mx0 = fmaxf(mx0, __shfl_xor_sync(0xffffffffu, mx0, 2));
    mx1 = fmaxf(mx1, __shfl_xor_sync(0xffffffffu, mx1, 1));
    mx1 = fmaxf(mx1, __shfl_xor_sync(0xffffffffu, mx1, 2));
    float sm0 = 0.f, sm1 = 0.f;
    #pragma unroll
    for (int nt = 0; nt < 13; nt++) {
        sacc[nt][0] = __expf(sacc[nt][0] - mx0);
        sacc[nt][1] = __expf(sacc[nt][1] - mx0);
        sacc[nt][2] = __expf(sacc[nt][2] - mx1);
        sacc[nt][3] = __expf(sacc[nt][3] - mx1);
        sm0 += sacc[nt][0] + sacc[nt][1];
        sm1 += sacc[nt][2] + sacc[nt][3];
    }
    sm0 += __shfl_xor_sync(0xffffffffu, sm0, 1);
    sm0 += __shfl_xor_sync(0xffffffffu, sm0, 2);
    sm1 += __shfl_xor_sync(0xffffffffu, sm1, 1);
    sm1 += __shfl_xor_sync(0xffffffffu, sm1, 2);
    float iv0 = 1.0f / sm0, iv1 = 1.0f / sm1;
    #pragma unroll
    for (int nt = 0; nt < 13; nt++) {
        sacc[nt][0] = tf32r(sacc[nt][0] * iv0);
        sacc[nt][1] = tf32r(sacc[nt][1] * iv0);
        sacc[nt][2] = tf32r(sacc[nt][2] * iv1);
        sacc[nt][3] = tf32r(sacc[nt][3] * iv1);
    }

    float oacc[4][4];
    #pragma unroll
    for (int vt = 0; vt < 4; vt++)
        #pragma unroll
        for (int t = 0; t < 4; t++) oacc[vt][t] = 0.0f;
    int qb = lane & ~3;
    int src0 = qb + (cc >> 1);
    bool odd = (cc & 1);
    #pragma unroll
    for (int kc = 0; kc < 13; kc++) {
        float p0 = sacc[kc][0], p1 = sacc[kc][1], p2 = sacc[kc][2], p3 = sacc[kc][3];
        float t0 = __shfl_sync(0xffffffffu, p0, src0);
        float t1 = __shfl_sync(0xffffffffu, p1, src0);
        float u0 = __shfl_sync(0xffffffffu, p0, src0 + 2);
        float u1 = __shfl_sync(0xffffffffu, p1, src0 + 2);
        float t2 = __shfl_sync(0xffffffffu, p2, src0);
        float t3 = __shfl_sync(0xffffffffu, p3, src0);
        float u2 = __shfl_sync(0xffffffffu, p2, src0 + 2);
        float u3 = __shfl_sync(0xffffffffu, p3, src0 + 2);
        uint32_t a0 = __float_as_uint(odd ? t1 : t0);
        uint32_t a2 = __float_as_uint(odd ? u1 : u0);
        uint32_t a1 = __float_as_uint(odd ? t3 : t2);
        uint32_t a3 = __float_as_uint(odd ? u3 : u2);
        int k0 = kc * 8;
        #pragma unroll
        for (int vt = 0; vt < 4; vt++) {
            uint32_t b0 = __float_as_uint(Vs[(k0 + cc) * 32     + ((vt * 8 + g) ^ (cc * 4))]);
            uint32_t b1 = __float_as_uint(Vs[(k0 + cc + 4) * 32 + ((vt * 8 + g) ^ (cc * 4 + 16))]);
            mma_tf32(oacc[vt], a0, a1, a2, a3, b0, b1);
        }
    }

    float* ob = g_attn + (size_t)win * NL * CD + h * 32;
    #pragma unroll
    for (int vt = 0; vt < 4; vt++) {
        int cb = vt * 8 + 2 * cc;
        if (r0 < NL) {
            float2 o; o.x = tf32r(oacc[vt][0]); o.y = tf32r(oacc[vt][1]);
            *reinterpret_cast<float2*>(ob + (size_t)r0 * CD + cb) = o;
        }
        if (r1 < NL) {
            float2 o; o.x = tf32r(oacc[vt][2]); o.y = tf32r(oacc[vt][3]);
            *reinterpret_cast<float2*>(ob + (size_t)r1 * CD + cb) = o;
        }
    }
}

// ---------------- launch ----------------
extern "C" void kernel_launch(void* const* d_in, const int* in_sizes, int n_in,
                              void* d_out, int out_size) {
    const float* x     = (const float*)d_in[0];
    const float* mask  = (const float*)d_in[1];
    const float* n1g   = (const float*)d_in[2];
    const float* n1b   = (const float*)d_in[3];
    const float* qkvw  = (const float*)d_in[4];
    const float* qkvb  = (const float*)d_in[5];
    const float* relb  = (const float*)d_in[6];
    const float* projw = (const float*)d_in[7];
    const float* projb = (const float*)d_in[8];
    const float* n2g   = (const float*)d_in[9];
    const float* n2b   = (const float*)d_in[10];
    const float* fc1w  = (const float*)d_in[11];
    const float* fc1b  = (const float*)d_in[12];
    const float* fc2w  = (const float*)d_in[13];
    const float* fc2b  = (const float*)d_in[14];
    float* out = (float*)d_out;

    void *p_xw, *p_qkv, *p_attn, *p_w;
    cudaGetSymbolAddress(&p_xw,   g_xw);
    cudaGetSymbolAddress(&p_qkv,  g_qkv);
    cudaGetSymbolAddress(&p_attn, g_attn);
    cudaGetSymbolAddress(&p_w,    g_wcvt);
    float* wc = (float*)p_w;

    cudaFuncSetAttribute(qkv_gemm,  cudaFuncAttributeMaxDynamicSharedMemorySize, GEMM_SMEM_DB);
    cudaFuncSetAttribute(proj_gemm, cudaFuncAttributeMaxDynamicSharedMemorySize, GEMM_SMEM_DB);
    cudaFuncSetAttribute(mlp_kernel, cudaFuncAttributeMaxDynamicSharedMemorySize, MLP_SMEM);

    cvt_kernel<<<(49152 + 255) / 256, 256>>>(qkvw, wc + W_QKV, 49152);
    cvt_kernel<<<(16384 + 255) / 256, 256>>>(projw, wc + W_PROJ, 16384);
    cvt_kernel<<<(65536 + 255) / 256, 256>>>(fc1w, wc + W_FC1, 65536);
    cvt_kernel<<<(65536 + 255) / 256, 256>>>(fc2w, wc + W_FC2, 65536);
    bias_kernel<<<(NHEAD * NL * NL + 255) / 256, 256>>>(relb);

    ln1_kernel<<<TOKENS / 8, 256>>>(x, n1g, n1b);
    qkv_gemm<<<dim3(3, TOKENS / 128), 256, GEMM_SMEM_DB>>>(
        (const float*)p_xw, wc + W_QKV, qkvb, (float*)p_qkv, 128, 384);
    attn_flash<<<dim3(NWIN, NHEAD), 224>>>(mask);
    proj_gemm<<<TOKENS / 128, 256, GEMM_SMEM_DB>>>(
        (const float*)p_attn, wc + W_PROJ, projb, x, n2g, n2b);
    mlp_kernel<<<TOKENS / 128, 256, MLP_SMEM>>>(
        wc + W_FC1, fc1b, wc + W_FC2, fc2b, out);
}

// round 8
// speedup vs baseline: 1.0760x; 1.0760x over previous
#include <cuda_runtime.h>
#include <math.h>
#include <stdint.h>

// ---------------- problem constants ----------------
#define TOKENS 200704          // 8*8*56*56
#define CD     128
#define NWIN   2048
#define NL     98
#define NHEAD  4

#define GEMM_SMEM_DB (4 * 16384)    // 64KB double-buffered gemm

// weight cvt offsets (floats)
#define W_QKV  0
#define W_PROJ 49152
#define W_FC1  65536
#define W_FC2  131072
#define W_TOT  196608

// ---------------- scratch ----------------
__device__ float g_xw  [(size_t)TOKENS * CD];
__device__ float g_qkv [(size_t)TOKENS * 3 * CD];
__device__ float g_bias[(size_t)NHEAD * NL * NL];
__device__ float g_attn[(size_t)TOKENS * CD];
__device__ float g_x2  [(size_t)TOKENS * CD];
__device__ float g_y   [(size_t)TOKENS * CD];
__device__ float g_hid [(size_t)TOKENS * 4 * CD];
__device__ float g_wcvt[W_TOT];

// ---------------- helpers ----------------
__device__ __forceinline__ float tf32r(float v) {
    uint32_t o;
    asm("cvt.rna.tf32.f32 %0, %1;" : "=r"(o) : "f"(v));
    return __uint_as_float(o);
}
__device__ __forceinline__ void mma_tf32(float c[4],
                                         uint32_t a0, uint32_t a1, uint32_t a2, uint32_t a3,
                                         uint32_t b0, uint32_t b1) {
    asm volatile(
        "mma.sync.aligned.m16n8k8.row.col.f32.tf32.tf32.f32 "
        "{%0,%1,%2,%3}, {%4,%5,%6,%7}, {%8,%9}, {%0,%1,%2,%3};\n"
        : "+f"(c[0]), "+f"(c[1]), "+f"(c[2]), "+f"(c[3])
        : "r"(a0), "r"(a1), "r"(a2), "r"(a3), "r"(b0), "r"(b1));
}
__device__ __forceinline__ uint32_t smem_u32(const void* p) {
    uint32_t a;
    asm("{ .reg .u64 t; cvta.to.shared.u64 t, %1; cvt.u32.u64 %0, t; }" : "=r"(a) : "l"(p));
    return a;
}
#define CP16(dst, src) \
    asm volatile("cp.async.cg.shared.global [%0], [%1], 16;\n" :: "r"(dst), "l"(src))
#define CP_COMMIT() asm volatile("cp.async.commit_group;\n" ::: "memory")
#define CP_WAIT(n)  asm volatile("cp.async.wait_group %0;\n" :: "n"(n) : "memory")

// one 128x128x32 mma sub-block
__device__ __forceinline__ void mma_chunk(const float* __restrict__ Ab,
                                          const float* __restrict__ Bb,
                                          float (*acc)[4][4],
                                          int wm, int wn, int g, int cc) {
    #pragma unroll
    for (int ks = 0; ks < 4; ks++) {
        int k0 = ks * 8;
        int sw = g * 4;
        uint32_t af[4][4];
        #pragma unroll
        for (int mt = 0; mt < 4; mt++) {
            int rb = wm * 64 + mt * 16 + g;
            af[mt][0] = __float_as_uint(Ab[rb * 32       + ((k0 + cc)     ^ sw)]);
            af[mt][1] = __float_as_uint(Ab[(rb + 8) * 32 + ((k0 + cc)     ^ sw)]);
            af[mt][2] = __float_as_uint(Ab[rb * 32       + ((k0 + cc + 4) ^ sw)]);
            af[mt][3] = __float_as_uint(Ab[(rb + 8) * 32 + ((k0 + cc + 4) ^ sw)]);
        }
        uint32_t bf[4][2];
        #pragma unroll
        for (int nt = 0; nt < 4; nt++) {
            int nb = wn * 32 + nt * 8 + g;
            bf[nt][0] = __float_as_uint(Bb[nb * 32 + ((k0 + cc)     ^ sw)]);
            bf[nt][1] = __float_as_uint(Bb[nb * 32 + ((k0 + cc + 4) ^ sw)]);
        }
        #pragma unroll
        for (int mt = 0; mt < 4; mt++)
            #pragma unroll
            for (int nt = 0; nt < 4; nt++)
                mma_tf32(acc[mt][nt], af[mt][0], af[mt][1], af[mt][2], af[mt][3],
                         bf[nt][0], bf[nt][1]);
    }
}

// window row -> spatial token
__device__ __forceinline__ int win_to_spatial(int gr) {
    int win = gr / NL, n = gr % NL;
    int bb = win >> 8, wl = win & 255;
    int dz = wl >> 6, hy = (wl >> 3) & 7, wx = wl & 7;
    int id = n / 49, ih = (n / 7) % 7, iw = n % 7;
    int d  = (dz * 2 + id + 1) & 7;
    int hh = hy * 7 + ih + 3; if (hh >= 56) hh -= 56;
    int ww = wx * 7 + iw + 3; if (ww >= 56) ww -= 56;
    return ((bb * 8 + d) * 56 + hh) * 56 + ww;
}

// ---------------- weight tf32 pre-conversion ----------------
__global__ void cvt_kernel(const float* __restrict__ in, float* __restrict__ out, int n) {
    int i = blockIdx.x * 256 + threadIdx.x;
    if (i < n) out[i] = tf32r(in[i]);
}

// ============ generic GEMM (double-buffered cp.async) =======================
// MODE 0: +bias; MODE 1: +bias, GELU, tf32 out; MODE 2: +bias, +residual
template<int MODE>
__global__ void __launch_bounds__(256, 2)
mma_gemm(const float* __restrict__ A, const float* __restrict__ W,
         const float* __restrict__ bias, const float* __restrict__ res,
         float* __restrict__ C, int K, int N) {
    extern __shared__ float gsm[];
    uint32_t sb = smem_u32(gsm);
    int tid = threadIdx.x;
    int wid = tid >> 5, lane = tid & 31;
    int g = lane >> 2, cc = lane & 3;
    int m0 = blockIdx.y * 128, n0 = blockIdx.x * 128;
    int wm = wid & 1, wn = wid >> 1;

    float acc[4][4][4];
    #pragma unroll
    for (int i = 0; i < 4; i++)
        #pragma unroll
        for (int j = 0; j < 4; j++)
            #pragma unroll
            for (int t = 0; t < 4; t++) acc[i][j][t] = 0.0f;

    int r_ld = tid >> 3, c4_ld = tid & 7;
    uint32_t soff_base = ((uint32_t)r_ld * 32 + (((uint32_t)c4_ld * 4) ^ ((r_ld & 7) * 4))) * 4;

    int nc = K >> 5;
    auto issue = [&](int kc, int buf) {
        int k0 = kc * 32;
        #pragma unroll
        for (int i = 0; i < 4; i++) {
            int r = r_ld + i * 32;
            uint32_t soff = soff_base + (uint32_t)i * 4096;
            CP16(sb + buf * 16384 + soff, A + (size_t)(m0 + r) * K + k0 + c4_ld * 4);
            CP16(sb + 32768 + buf * 16384 + soff, W + (size_t)(n0 + r) * K + k0 + c4_ld * 4);
        }
        CP_COMMIT();
    };

    issue(0, 0);
    for (int kc = 0; kc < nc; kc++) {
        if (kc + 1 < nc) { issue(kc + 1, (kc + 1) & 1); CP_WAIT(1); }
        else             { CP_WAIT(0); }
        __syncthreads();
        mma_chunk(gsm + (kc & 1) * 4096, gsm + 8192 + (kc & 1) * 4096, acc, wm, wn, g, cc);
        __syncthreads();
    }

    #pragma unroll
    for (int mt = 0; mt < 4; mt++) {
        int r0 = m0 + wm * 64 + mt * 16 + g;
        #pragma unroll
        for (int nt = 0; nt < 4; nt++) {
            int cb = n0 + wn * 32 + nt * 8 + cc * 2;
            float2 bb = *reinterpret_cast<const float2*>(bias + cb);
            #pragma unroll
            for (int hrow = 0; hrow < 2; hrow++) {
                int row = r0 + hrow * 8;
                float v0 = acc[mt][nt][hrow * 2 + 0] + bb.x;
                float v1 = acc[mt][nt][hrow * 2 + 1] + bb.y;
                if (MODE == 1) {
                    v0 = tf32r(0.5f * v0 * (1.0f + erff(v0 * 0.70710678118654752f)));
                    v1 = tf32r(0.5f * v1 * (1.0f + erff(v1 * 0.70710678118654752f)));
                }
                if (MODE == 2) {
                    float2 r2 = *reinterpret_cast<const float2*>(res + (size_t)row * N + cb);
                    v0 += r2.x; v1 += r2.y;
                }
                float2 o; o.x = v0; o.y = v1;
                *reinterpret_cast<float2*>(C + (size_t)row * N + cb) = o;
            }
        }
    }
}

// ============ proj GEMM + residual + LN2 fused epilogue =====================
__global__ void __launch_bounds__(256, 2)
proj_gemm(const float* __restrict__ A, const float* __restrict__ W,
          const float* __restrict__ bias, const float* __restrict__ x,
          const float* __restrict__ n2g, const float* __restrict__ n2b) {
    extern __shared__ float gsm[];
    __shared__ float rs1[128];
    __shared__ float rs2[128];
    uint32_t sb = smem_u32(gsm);
    int tid = threadIdx.x;
    int wid = tid >> 5, lane = tid & 31;
    int g = lane >> 2, cc = lane & 3;
    int m0 = blockIdx.x * 128;
    int wm = wid & 1, wn = wid >> 1;

    float acc[4][4][4];
    #pragma unroll
    for (int i = 0; i < 4; i++)
        #pragma unroll
        for (int j = 0; j < 4; j++)
            #pragma unroll
            for (int t = 0; t < 4; t++) acc[i][j][t] = 0.0f;

    int r_ld = tid >> 3, c4_ld = tid & 7;
    uint32_t soff_base = ((uint32_t)r_ld * 32 + (((uint32_t)c4_ld * 4) ^ ((r_ld & 7) * 4))) * 4;

    auto issue = [&](int kc, int buf) {
        int k0 = kc * 32;
        #pragma unroll
        for (int i = 0; i < 4; i++) {
            int r = r_ld + i * 32;
            uint32_t soff = soff_base + (uint32_t)i * 4096;
            CP16(sb + buf * 16384 + soff, A + (size_t)(m0 + r) * 128 + k0 + c4_ld * 4);
            CP16(sb + 32768 + buf * 16384 + soff, W + (size_t)r * 128 + k0 + c4_ld * 4);
        }
        CP_COMMIT();
    };

    if (tid < 128) { rs1[tid] = 0.0f; rs2[tid] = 0.0f; }

    issue(0, 0);
    for (int kc = 0; kc < 4; kc++) {
        if (kc + 1 < 4) { issue(kc + 1, (kc + 1) & 1); CP_WAIT(1); }
        else            { CP_WAIT(0); }
        __syncthreads();
        mma_chunk(gsm + (kc & 1) * 4096, gsm + 8192 + (kc & 1) * 4096, acc, wm, wn, g, cc);
        __syncthreads();
    }

    int tsp[4][2];
    #pragma unroll
    for (int mt = 0; mt < 4; mt++) {
        int rl = wm * 64 + mt * 16 + g;
        tsp[mt][0] = win_to_spatial(m0 + rl);
        tsp[mt][1] = win_to_spatial(m0 + rl + 8);
    }

    #pragma unroll
    for (int mt = 0; mt < 4; mt++) {
        #pragma unroll
        for (int hrow = 0; hrow < 2; hrow++) {
            int rl = wm * 64 + mt * 16 + g + hrow * 8;
            float s1 = 0.0f, s2 = 0.0f;
            #pragma unroll
            for (int nt = 0; nt < 4; nt++) {
                int cb = wn * 32 + nt * 8 + cc * 2;
                float2 bb = *reinterpret_cast<const float2*>(bias + cb);
                float2 xv = *reinterpret_cast<const float2*>(x + (size_t)tsp[mt][hrow] * CD + cb);
                float v0 = acc[mt][nt][hrow * 2 + 0] + bb.x + xv.x;
                float v1 = acc[mt][nt][hrow * 2 + 1] + bb.y + xv.y;
                acc[mt][nt][hrow * 2 + 0] = v0;
                acc[mt][nt][hrow * 2 + 1] = v1;
                s1 += v0 + v1;
                s2 += v0 * v0 + v1 * v1;
            }
            atomicAdd(&rs1[rl], s1);
            atomicAdd(&rs2[rl], s2);
        }
    }
    __syncthreads();

    #pragma unroll
    for (int mt = 0; mt < 4; mt++) {
        #pragma unroll
        for (int hrow = 0; hrow < 2; hrow++) {
            int rl = wm * 64 + mt * 16 + g + hrow * 8;
            int t_sp = tsp[mt][hrow];
            float mean = rs1[rl] * (1.0f / 128.0f);
            float var  = rs2[rl] * (1.0f / 128.0f) - mean * mean;
            float inv  = rsqrtf(var + 1e-5f);
            #pragma unroll
            for (int nt = 0; nt < 4; nt++) {
                int cb = wn * 32 + nt * 8 + cc * 2;
                float v0 = acc[mt][nt][hrow * 2 + 0];
                float v1 = acc[mt][nt][hrow * 2 + 1];
                float2 gg = *reinterpret_cast<const float2*>(n2g + cb);
                float2 bv = *reinterpret_cast<const float2*>(n2b + cb);
                float2 x2o; x2o.x = v0; x2o.y = v1;
                *reinterpret_cast<float2*>(g_x2 + (size_t)t_sp * CD + cb) = x2o;
                float2 yo;
                yo.x = tf32r((v0 - mean) * inv * gg.x + bv.x);
                yo.y = tf32r((v1 - mean) * inv * gg.y + bv.y);
                *reinterpret_cast<float2*>(g_y + (size_t)t_sp * CD + cb) = yo;
            }
        }
    }
}

// ---------------- rel-pos bias materialization ----------------
__global__ void bias_kernel(const float* __restrict__ rel_bias) {
    int t = blockIdx.x * blockDim.x + threadIdx.x;
    if (t >= NHEAD * NL * NL) return;
    int h = t / (NL * NL);
    int r = t % (NL * NL);
    int n = r / NL, m = r % NL;
    int id = n / 49, ih = (n / 7) % 7, iw = n % 7;
    int jd = m / 49, jh = (m / 7) % 7, jw = m % 7;
    int ridx = (id - jd + 1) * 169 + (ih - jh + 6) * 13 + (iw - jw + 6);
    g_bias[t] = rel_bias[ridx * NHEAD + h];
}

// ---------------- LN1 + shift + window partition (tf32 out) ----------------
__global__ void ln1_kernel(const float* __restrict__ x,
                           const float* __restrict__ g, const float* __restrict__ b) {
    int warp = blockIdx.x * 8 + (threadIdx.x >> 5);
    int lane = threadIdx.x & 31;
    if (warp >= TOKENS) return;
    int src = win_to_spatial(warp);
    float4 v = reinterpret_cast<const float4*>(x + (size_t)src * CD)[lane];
    float s1 = v.x + v.y + v.z + v.w;
    float s2 = v.x*v.x + v.y*v.y + v.z*v.z + v.w*v.w;
    #pragma unroll
    for (int o = 16; o; o >>= 1) {
        s1 += __shfl_xor_sync(0xffffffffu, s1, o);
        s2 += __shfl_xor_sync(0xffffffffu, s2, o);
    }
    float mean = s1 * (1.0f / 128.0f);
    float var  = s2 * (1.0f / 128.0f) - mean * mean;
    float inv  = rsqrtf(var + 1e-5f);
    float4 gg = reinterpret_cast<const float4*>(g)[lane];
    float4 bv = reinterpret_cast<const float4*>(b)[lane];
    float4 o;
    o.x = tf32r((v.x - mean) * inv * gg.x + bv.x);
    o.y = tf32r((v.y - mean) * inv * gg.y + bv.y);
    o.z = tf32r((v.z - mean) * inv * gg.z + bv.z);
    o.w = tf32r((v.w - mean) * inv * gg.w + bv.w);
    reinterpret_cast<float4*>(g_xw)[(size_t)warp * 32 + lane] = o;
}

// ---------------- flash-style register attention ----------------
__global__ void __launch_bounds__(224, 2)
attn_flash(const float* __restrict__ mask) {
    __shared__ float Qs[112 * 32];
    __shared__ float Ks[104 * 32];
    __shared__ float Vs[104 * 32];
    int win = blockIdx.x, h = blockIdx.y;
    int tid = threadIdx.x, wid = tid >> 5, lane = tid & 31;
    int g = lane >> 2, cc = lane & 3;

    for (int i = tid; i < 14 * 32; i += 224) Qs[98 * 32 + i] = 0.0f;
    if (tid < 192) { Ks[98 * 32 + tid] = 0.0f; Vs[98 * 32 + tid] = 0.0f; }
    const float* base = g_qkv + (size_t)win * NL * 384 + h * 32;
    for (int e = tid; e < 98 * 24; e += 224) {
        int tok = e / 24, p = e - tok * 24;
        int which = p >> 3, c4 = p & 7;
        float4 v = *reinterpret_cast<const float4*>(base + (size_t)tok * 384 + which * 128 + c4 * 4);
        if (which == 0) {
            const float sc = 0.17677669529663689f;
            v.x *= sc; v.y *= sc; v.z *= sc; v.w *= sc;
        }
        float4 t;
        t.x = tf32r(v.x); t.y = tf32r(v.y); t.z = tf32r(v.z); t.w = tf32r(v.w);
        int col = (c4 * 4) ^ ((tok & 7) * 4);
        float* dst = (which == 0 ? Qs : which == 1 ? Ks : Vs) + tok * 32 + col;
        *reinterpret_cast<float4*>(dst) = t;
    }
    __syncthreads();

    int m0 = wid * 16;
    int r0 = m0 + g, r1 = m0 + g + 8;
    int sw = g * 4;

    uint32_t aq[4][4];
    #pragma unroll
    for (int kc = 0; kc < 4; kc++) {
        int col0 = (kc * 8 + cc) ^ sw;
        int col1 = (kc * 8 + cc + 4) ^ sw;
        aq[kc][0] = __float_as_uint(Qs[r0 * 32 + col0]);
        aq[kc][1] = __float_as_uint(Qs[r1 * 32 + col0]);
        aq[kc][2] = __float_as_uint(Qs[r0 * 32 + col1]);
        aq[kc][3] = __float_as_uint(Qs[r1 * 32 + col1]);
    }

    float sacc[13][4];
    #pragma unroll
    for (int nt = 0; nt < 13; nt++) {
        float s[4] = {0.f, 0.f, 0.f, 0.f};
        int nr = nt * 8 + g;
        #pragma unroll
        for (int kc = 0; kc < 4; kc++) {
            int col0 = (kc * 8 + cc) ^ sw;
            int col1 = (kc * 8 + cc + 4) ^ sw;
            uint32_t b0 = __float_as_uint(Ks[nr * 32 + col0]);
            uint32_t b1 = __float_as_uint(Ks[nr * 32 + col1]);
            mma_tf32(s, aq[kc][0], aq[kc][1], aq[kc][2], aq[kc][3], b0, b1);
        }
        sacc[nt][0] = s[0]; sacc[nt][1] = s[1]; sacc[nt][2] = s[2]; sacc[nt][3] = s[3];
    }

    {
        const float* bm = g_bias + (size_t)h * (NL * NL);
        const float* mk = mask + (size_t)(win & 255) * (NL * NL);
        int rc0 = (r0 < 98 ? r0 : 97) * 98;
        int rc1 = (r1 < 98 ? r1 : 97) * 98;
        #pragma unroll
        for (int nt = 0; nt < 13; nt++) {
            int col = nt * 8 + 2 * cc;
            if (col < 98) {
                sacc[nt][0] += __ldg(bm + rc0 + col) + __ldg(mk + rc0 + col);
                sacc[nt][2] += __ldg(bm + rc1 + col) + __ldg(mk + rc1 + col);
            } else { sacc[nt][0] = -1.0e38f; sacc[nt][2] = -1.0e38f; }
            if (col + 1 < 98) {
                sacc[nt][1] += __ldg(bm + rc0 + col + 1) + __ldg(mk + rc0 + col + 1);
                sacc[nt][3] += __ldg(bm + rc1 + col + 1) + __ldg(mk + rc1 + col + 1);
            } else { sacc[nt][1] = -1.0e38f; sacc[nt][3] = -1.0e38f; }
        }
    }

    float mx0 = -1.0e38f, mx1 = -1.0e38f;
    #pragma unroll
    for (int nt = 0; nt < 13; nt++) {
        mx0 = fmaxf(mx0, fmaxf(sacc[nt][0], sacc[nt][1]));
        mx1 = fmaxf(mx1, fmaxf(sacc[nt][2], sacc[nt][3]));
    }
    mx0 = fmaxf(mx0, __shfl_xor_sync(0xffffffffu, mx0, 1));
    mx0 = fmaxf(mx0, __shfl_xor_sync(0xffffffffu, mx0, 2));
    mx1 = fmaxf(mx1, __shfl_xor_sync(0xffffffffu, mx1, 1));
    mx1 = fmaxf(mx1, __shfl_xor_sync(0xffffffffu, mx1, 2));
    float sm0 = 0.f, sm1 = 0.f;
    #pragma unroll
    for (int nt = 0; nt < 13; nt++) {
        sacc[nt][0] = __expf(sacc[nt][0] - mx0);
        sacc[nt][1] = __expf(sacc[nt][1] - mx0);
        sacc[nt][2] = __expf(sacc[nt][2] - mx1);
        sacc[nt][3] = __expf(sacc[nt][3] - mx1);
        sm0 += sacc[nt][0] + sacc[nt][1];
        sm1 += sacc[nt][2] + sacc[nt][3];
    }
    sm0 += __shfl_xor_sync(0xffffffffu, sm0, 1);
    sm0 += __shfl_xor_sync(0xffffffffu, sm0, 2);
    sm1 += __shfl_xor_sync(0xffffffffu, sm1, 1);
    sm1 += __shfl_xor_sync(0xffffffffu, sm1, 2);
    float iv0 = 1.0f / sm0, iv1 = 1.0f / sm1;
    #pragma unroll
    for (int nt = 0; nt < 13; nt++) {
        sacc[nt][0] = tf32r(sacc[nt][0] * iv0);
        sacc[nt][1] = tf32r(sacc[nt][1] * iv0);
        sacc[nt][2] = tf32r(sacc[nt][2] * iv1);
        sacc[nt][3] = tf32r(sacc[nt][3] * iv1);
    }

    float oacc[4][4];
    #pragma unroll
    for (int vt = 0; vt < 4; vt++)
        #pragma unroll
        for (int t = 0; t < 4; t++) oacc[vt][t] = 0.0f;
    int qb = lane & ~3;
    int src0 = qb + (cc >> 1);
    bool odd = (cc & 1);
    #pragma unroll
    for (int kc = 0; kc < 13; kc++) {
        float p0 = sacc[kc][0], p1 = sacc[kc][1], p2 = sacc[kc][2], p3 = sacc[kc][3];
        float t0 = __shfl_sync(0xffffffffu, p0, src0);
        float t1 = __shfl_sync(0xffffffffu, p1, src0);
        float u0 = __shfl_sync(0xffffffffu, p0, src0 + 2);
        float u1 = __shfl_sync(0xffffffffu, p1, src0 + 2);
        float t2 = __shfl_sync(0xffffffffu, p2, src0);
        float t3 = __shfl_sync(0xffffffffu, p3, src0);
        float u2 = __shfl_sync(0xffffffffu, p2, src0 + 2);
        float u3 = __shfl_sync(0xffffffffu, p3, src0 + 2);
        uint32_t a0 = __float_as_uint(odd ? t1 : t0);
        uint32_t a2 = __float_as_uint(odd ? u1 : u0);
        uint32_t a1 = __float_as_uint(odd ? t3 : t2);
        uint32_t a3 = __float_as_uint(odd ? u3 : u2);
        int k0 = kc * 8;
        #pragma unroll
        for (int vt = 0; vt < 4; vt++) {
            uint32_t b0 = __float_as_uint(Vs[(k0 + cc) * 32     + ((vt * 8 + g) ^ (cc * 4))]);
            uint32_t b1 = __float_as_uint(Vs[(k0 + cc + 4) * 32 + ((vt * 8 + g) ^ (cc * 4 + 16))]);
            mma_tf32(oacc[vt], a0, a1, a2, a3, b0, b1);
        }
    }

    float* ob = g_attn + (size_t)win * NL * CD + h * 32;
    #pragma unroll
    for (int vt = 0; vt < 4; vt++) {
        int cb = vt * 8 + 2 * cc;
        if (r0 < NL) {
            float2 o; o.x = tf32r(oacc[vt][0]); o.y = tf32r(oacc[vt][1]);
            *reinterpret_cast<float2*>(ob + (size_t)r0 * CD + cb) = o;
        }
        if (r1 < NL) {
            float2 o; o.x = tf32r(oacc[vt][2]); o.y = tf32r(oacc[vt][3]);
            *reinterpret_cast<float2*>(ob + (size_t)r1 * CD + cb) = o;
        }
    }
}

// ---------------- launch ----------------
extern "C" void kernel_launch(void* const* d_in, const int* in_sizes, int n_in,
                              void* d_out, int out_size) {
    const float* x     = (const float*)d_in[0];
    const float* mask  = (const float*)d_in[1];
    const float* n1g   = (const float*)d_in[2];
    const float* n1b   = (const float*)d_in[3];
    const float* qkvw  = (const float*)d_in[4];
    const float* qkvb  = (const float*)d_in[5];
    const float* relb  = (const float*)d_in[6];
    const float* projw = (const float*)d_in[7];
    const float* projb = (const float*)d_in[8];
    const float* n2g   = (const float*)d_in[9];
    const float* n2b   = (const float*)d_in[10];
    const float* fc1w  = (const float*)d_in[11];
    const float* fc1b  = (const float*)d_in[12];
    const float* fc2w  = (const float*)d_in[13];
    const float* fc2b  = (const float*)d_in[14];
    float* out = (float*)d_out;

    void *p_xw, *p_qkv, *p_attn, *p_x2, *p_y, *p_hid, *p_w;
    cudaGetSymbolAddress(&p_xw,   g_xw);
    cudaGetSymbolAddress(&p_qkv,  g_qkv);
    cudaGetSymbolAddress(&p_attn, g_attn);
    cudaGetSymbolAddress(&p_x2,   g_x2);
    cudaGetSymbolAddress(&p_y,    g_y);
    cudaGetSymbolAddress(&p_hid,  g_hid);
    cudaGetSymbolAddress(&p_w,    g_wcvt);
    float* wc = (float*)p_w;

    cudaFuncSetAttribute(mma_gemm<0>, cudaFuncAttributeMaxDynamicSharedMemorySize, GEMM_SMEM_DB);
    cudaFuncSetAttribute(mma_gemm<1>, cudaFuncAttributeMaxDynamicSharedMemorySize, GEMM_SMEM_DB);
    cudaFuncSetAttribute(mma_gemm<2>, cudaFuncAttributeMaxDynamicSharedMemorySize, GEMM_SMEM_DB);
    cudaFuncSetAttribute(proj_gemm,   cudaFuncAttributeMaxDynamicSharedMemorySize, GEMM_SMEM_DB);

    cvt_kernel<<<(49152 + 255) / 256, 256>>>(qkvw, wc + W_QKV, 49152);
    cvt_kernel<<<(16384 + 255) / 256, 256>>>(projw, wc + W_PROJ, 16384);
    cvt_kernel<<<(65536 + 255) / 256, 256>>>(fc1w, wc + W_FC1, 65536);
    cvt_kernel<<<(65536 + 255) / 256, 256>>>(fc2w, wc + W_FC2, 65536);
    bias_kernel<<<(NHEAD * NL * NL + 255) / 256, 256>>>(relb);

    ln1_kernel<<<TOKENS / 8, 256>>>(x, n1g, n1b);
    qkv_gemm_launch:
    mma_gemm<0><<<dim3(3, TOKENS / 128), 256, GEMM_SMEM_DB>>>(
        (const float*)p_xw, wc + W_QKV, qkvb, nullptr, (float*)p_qkv, 128, 384);
    attn_flash<<<dim3(NWIN, NHEAD), 224>>>(mask);
    proj_gemm<<<TOKENS / 128, 256, GEMM_SMEM_DB>>>(
        (const float*)p_attn, wc + W_PROJ, projb, x, n2g, n2b);
    // fc1 + GELU -> g_hid (tf32)
    mma_gemm<1><<<dim3(4, TOKENS / 128), 256, GEMM_SMEM_DB>>>(
        (const float*)p_y, wc + W_FC1, fc1b, nullptr, (float*)p_hid, 128, 512);
    // fc2 + residual -> out
    mma_gemm<2><<<dim3(1, TOKENS / 128), 256, GEMM_SMEM_DB>>>(
        (const float*)p_hid, wc + W_FC2, fc2b, (const float*)p_x2, out, 512, 128);
}

// round 9
// speedup vs baseline: 1.0908x; 1.0138x over previous
#include <cuda_runtime.h>
#include <math.h>
#include <stdint.h>

// ---------------- problem constants ----------------
#define TOKENS 200704          // 8*8*56*56
#define CD     128
#define NWIN   2048
#define NL     98
#define NHEAD  4

#define GEMM_SMEM_DB (4 * 16384)    // 64KB double-buffered gemm (proj/fc2)
#define GEMM_SMEM_AR (6 * 16384)    // 96KB: A-resident (64KB) + W double buffer (32KB)

// weight cvt offsets (floats)
#define W_QKV  0
#define W_PROJ 49152
#define W_FC1  65536
#define W_FC2  131072
#define W_TOT  196608

// ---------------- scratch ----------------
__device__ float g_qkv [(size_t)TOKENS * 3 * CD];
__device__ float g_bias[(size_t)NHEAD * NL * NL];
__device__ float g_attn[(size_t)TOKENS * CD];
__device__ float g_x2  [(size_t)TOKENS * CD];
__device__ float g_y   [(size_t)TOKENS * CD];
__device__ float g_hid [(size_t)TOKENS * 4 * CD];
__device__ float g_wcvt[W_TOT];

// ---------------- helpers ----------------
__device__ __forceinline__ float tf32r(float v) {
    uint32_t o;
    asm("cvt.rna.tf32.f32 %0, %1;" : "=r"(o) : "f"(v));
    return __uint_as_float(o);
}
__device__ __forceinline__ void mma_tf32(float c[4],
                                         uint32_t a0, uint32_t a1, uint32_t a2, uint32_t a3,
                                         uint32_t b0, uint32_t b1) {
    asm volatile(
        "mma.sync.aligned.m16n8k8.row.col.f32.tf32.tf32.f32 "
        "{%0,%1,%2,%3}, {%4,%5,%6,%7}, {%8,%9}, {%0,%1,%2,%3};\n"
        : "+f"(c[0]), "+f"(c[1]), "+f"(c[2]), "+f"(c[3])
        : "r"(a0), "r"(a1), "r"(a2), "r"(a3), "r"(b0), "r"(b1));
}
__device__ __forceinline__ uint32_t smem_u32(const void* p) {
    uint32_t a;
    asm("{ .reg .u64 t; cvta.to.shared.u64 t, %1; cvt.u32.u64 %0, t; }" : "=r"(a) : "l"(p));
    return a;
}
#define CP16(dst, src) \
    asm volatile("cp.async.cg.shared.global [%0], [%1], 16;\n" :: "r"(dst), "l"(src))
#define CP_COMMIT() asm volatile("cp.async.commit_group;\n" ::: "memory")
#define CP_WAIT(n)  asm volatile("cp.async.wait_group %0;\n" :: "n"(n) : "memory")

// one 128x128x32 mma sub-block
__device__ __forceinline__ void mma_chunk(const float* __restrict__ Ab,
                                          const float* __restrict__ Bb,
                                          float (*acc)[4][4],
                                          int wm, int wn, int g, int cc) {
    #pragma unroll
    for (int ks = 0; ks < 4; ks++) {
        int k0 = ks * 8;
        int sw = g * 4;
        uint32_t af[4][4];
        #pragma unroll
        for (int mt = 0; mt < 4; mt++) {
            int rb = wm * 64 + mt * 16 + g;
            af[mt][0] = __float_as_uint(Ab[rb * 32       + ((k0 + cc)     ^ sw)]);
            af[mt][1] = __float_as_uint(Ab[(rb + 8) * 32 + ((k0 + cc)     ^ sw)]);
            af[mt][2] = __float_as_uint(Ab[rb * 32       + ((k0 + cc + 4) ^ sw)]);
            af[mt][3] = __float_as_uint(Ab[(rb + 8) * 32 + ((k0 + cc + 4) ^ sw)]);
        }
        uint32_t bf[4][2];
        #pragma unroll
        for (int nt = 0; nt < 4; nt++) {
            int nb = wn * 32 + nt * 8 + g;
            bf[nt][0] = __float_as_uint(Bb[nb * 32 + ((k0 + cc)     ^ sw)]);
            bf[nt][1] = __float_as_uint(Bb[nb * 32 + ((k0 + cc + 4) ^ sw)]);
        }
        #pragma unroll
        for (int mt = 0; mt < 4; mt++)
            #pragma unroll
            for (int nt = 0; nt < 4; nt++)
                mma_tf32(acc[mt][nt], af[mt][0], af[mt][1], af[mt][2], af[mt][3],
                         bf[nt][0], bf[nt][1]);
    }
}

// window row -> spatial token
__device__ __forceinline__ int win_to_spatial(int gr) {
    int win = gr / NL, n = gr % NL;
    int bb = win >> 8, wl = win & 255;
    int dz = wl >> 6, hy = (wl >> 3) & 7, wx = wl & 7;
    int id = n / 49, ih = (n / 7) % 7, iw = n % 7;
    int d  = (dz * 2 + id + 1) & 7;
    int hh = hy * 7 + ih + 3; if (hh >= 56) hh -= 56;
    int ww = wx * 7 + iw + 3; if (ww >= 56) ww -= 56;
    return ((bb * 8 + d) * 56 + hh) * 56 + ww;
}

// ---------------- weight tf32 pre-conversion ----------------
__global__ void cvt_kernel(const float* __restrict__ in, float* __restrict__ out, int n) {
    int i = blockIdx.x * 256 + threadIdx.x;
    if (i < n) out[i] = tf32r(in[i]);
}

// ============ QKV: fused LN1-gather + A-resident GEMM over 3 N-tiles ========
// smem: A[4 chunks][128][32] (64KB) | W[2 bufs][128][32] (32KB)
__global__ void __launch_bounds__(256, 2)
qkv_ln_gemm(const float* __restrict__ x,
            const float* __restrict__ n1g, const float* __restrict__ n1b,
            const float* __restrict__ W, const float* __restrict__ bias,
            float* __restrict__ C) {
    extern __shared__ float gsm[];
    uint32_t sb = smem_u32(gsm);
    const uint32_t WOFF = 65536u;      // bytes
    int tid = threadIdx.x;
    int wid = tid >> 5, lane = tid & 31;
    int g = lane >> 2, cc = lane & 3;
    int m0 = blockIdx.x * 128;
    int wm = wid & 1, wn = wid >> 1;

    // ---- phase 1: gather + LN1 -> A smem (tf32, swizzled) ----
    {
        float4 gg = reinterpret_cast<const float4*>(n1g)[lane];
        float4 bv = reinterpret_cast<const float4*>(n1b)[lane];
        int cchunk = lane >> 3;
        int colbase = (lane * 4) & 31;
        for (int r = wid; r < 128; r += 8) {
            int src = win_to_spatial(m0 + r);
            float4 v = reinterpret_cast<const float4*>(x + (size_t)src * CD)[lane];
            float s1 = v.x + v.y + v.z + v.w;
            float s2 = v.x*v.x + v.y*v.y + v.z*v.z + v.w*v.w;
            #pragma unroll
            for (int o = 16; o; o >>= 1) {
                s1 += __shfl_xor_sync(0xffffffffu, s1, o);
                s2 += __shfl_xor_sync(0xffffffffu, s2, o);
            }
            float mean = s1 * (1.0f / 128.0f);
            float var  = s2 * (1.0f / 128.0f) - mean * mean;
            float inv  = rsqrtf(var + 1e-5f);
            float4 o;
            o.x = tf32r((v.x - mean) * inv * gg.x + bv.x);
            o.y = tf32r((v.y - mean) * inv * gg.y + bv.y);
            o.z = tf32r((v.z - mean) * inv * gg.z + bv.z);
            o.w = tf32r((v.w - mean) * inv * gg.w + bv.w);
            int col = colbase ^ ((r & 7) * 4);
            *reinterpret_cast<float4*>(gsm + cchunk * 4096 + r * 32 + col) = o;
        }
    }
    __syncthreads();

    // ---- phase 2: loop 3 N-tiles, stream W ----
    int r_ld = tid >> 3, c4_ld = tid & 7;
    uint32_t soff_base = ((uint32_t)r_ld * 32 + (((uint32_t)c4_ld * 4) ^ ((r_ld & 7) * 4))) * 4;

    for (int nb = 0; nb < 3; nb++) {
        int n0 = nb * 128;
        auto issueW = [&](int kc, int buf) {
            #pragma unroll
            for (int i = 0; i < 4; i++) {
                int r = r_ld + i * 32;
                uint32_t soff = soff_base + (uint32_t)i * 4096;
                CP16(sb + WOFF + (uint32_t)buf * 16384 + soff,
                     W + (size_t)(n0 + r) * 128 + kc * 32 + c4_ld * 4);
            }
            CP_COMMIT();
        };

        float acc[4][4][4];
        #pragma unroll
        for (int i = 0; i < 4; i++)
            #pragma unroll
            for (int j = 0; j < 4; j++)
                #pragma unroll
                for (int t = 0; t < 4; t++) acc[i][j][t] = 0.0f;

        issueW(0, 0);
        for (int kc = 0; kc < 4; kc++) {
            if (kc + 1 < 4) { issueW(kc + 1, (kc + 1) & 1); CP_WAIT(1); }
            else            { CP_WAIT(0); }
            __syncthreads();
            mma_chunk(gsm + kc * 4096, gsm + 16384 + (kc & 1) * 4096, acc, wm, wn, g, cc);
            __syncthreads();
        }

        #pragma unroll
        for (int mt = 0; mt < 4; mt++) {
            int r0 = m0 + wm * 64 + mt * 16 + g;
            #pragma unroll
            for (int nt = 0; nt < 4; nt++) {
                int cb = n0 + wn * 32 + nt * 8 + cc * 2;
                float2 bb = *reinterpret_cast<const float2*>(bias + cb);
                #pragma unroll
                for (int hrow = 0; hrow < 2; hrow++) {
                    int row = r0 + hrow * 8;
                    float2 o;
                    o.x = acc[mt][nt][hrow * 2 + 0] + bb.x;
                    o.y = acc[mt][nt][hrow * 2 + 1] + bb.y;
                    *reinterpret_cast<float2*>(C + (size_t)row * 384 + cb) = o;
                }
            }
        }
    }
}

// ============ fc1: A-resident GEMM over 4 N-tiles, GELU epilogue ============
__global__ void __launch_bounds__(256, 2)
fc1_gemm(const float* __restrict__ W, const float* __restrict__ bias,
         float* __restrict__ C) {
    extern __shared__ float gsm[];
    uint32_t sb = smem_u32(gsm);
    const uint32_t WOFF = 65536u;
    int tid = threadIdx.x;
    int wid = tid >> 5, lane = tid & 31;
    int g = lane >> 2, cc = lane & 3;
    int m0 = blockIdx.x * 128;
    int wm = wid & 1, wn = wid >> 1;

    int r_ld = tid >> 3, c4_ld = tid & 7;
    uint32_t soff_base = ((uint32_t)r_ld * 32 + (((uint32_t)c4_ld * 4) ^ ((r_ld & 7) * 4))) * 4;

    // issue full A tile (g_y rows, already tf32) as one group
    #pragma unroll
    for (int c = 0; c < 4; c++) {
        #pragma unroll
        for (int i = 0; i < 4; i++) {
            int r = r_ld + i * 32;
            uint32_t soff = soff_base + (uint32_t)i * 4096;
            CP16(sb + (uint32_t)c * 16384 + soff,
                 g_y + (size_t)(m0 + r) * 128 + c * 32 + c4_ld * 4);
        }
    }
    CP_COMMIT();

    for (int nb = 0; nb < 4; nb++) {
        int n0 = nb * 128;
        auto issueW = [&](int kc, int buf) {
            #pragma unroll
            for (int i = 0; i < 4; i++) {
                int r = r_ld + i * 32;
                uint32_t soff = soff_base + (uint32_t)i * 4096;
                CP16(sb + WOFF + (uint32_t)buf * 16384 + soff,
                     W + (size_t)(n0 + r) * 128 + kc * 32 + c4_ld * 4);
            }
            CP_COMMIT();
        };

        float acc[4][4][4];
        #pragma unroll
        for (int i = 0; i < 4; i++)
            #pragma unroll
            for (int j = 0; j < 4; j++)
                #pragma unroll
                for (int t = 0; t < 4; t++) acc[i][j][t] = 0.0f;

        issueW(0, 0);
        for (int kc = 0; kc < 4; kc++) {
            if (kc + 1 < 4) { issueW(kc + 1, (kc + 1) & 1); CP_WAIT(1); }
            else            { CP_WAIT(0); }
            __syncthreads();
            mma_chunk(gsm + kc * 4096, gsm + 16384 + (kc & 1) * 4096, acc, wm, wn, g, cc);
            __syncthreads();
        }

        #pragma unroll
        for (int mt = 0; mt < 4; mt++) {
            int r0 = m0 + wm * 64 + mt * 16 + g;
            #pragma unroll
            for (int nt = 0; nt < 4; nt++) {
                int cb = n0 + wn * 32 + nt * 8 + cc * 2;
                float2 bb = *reinterpret_cast<const float2*>(bias + cb);
                #pragma unroll
                for (int hrow = 0; hrow < 2; hrow++) {
                    int row = r0 + hrow * 8;
                    float v0 = acc[mt][nt][hrow * 2 + 0] + bb.x;
                    float v1 = acc[mt][nt][hrow * 2 + 1] + bb.y;
                    v0 = tf32r(0.5f * v0 * (1.0f + erff(v0 * 0.70710678118654752f)));
                    v1 = tf32r(0.5f * v1 * (1.0f + erff(v1 * 0.70710678118654752f)));
                    float2 o; o.x = v0; o.y = v1;
                    *reinterpret_cast<float2*>(C + (size_t)row * 512 + cb) = o;
                }
            }
        }
    }
}

// ============ fc2 GEMM (double-buffered, +bias +residual) ===================
__global__ void __launch_bounds__(256, 2)
fc2_gemm(const float* __restrict__ A, const float* __restrict__ W,
         const float* __restrict__ bias, const float* __restrict__ res,
         float* __restrict__ C) {
    extern __shared__ float gsm[];
    uint32_t sb = smem_u32(gsm);
    int tid = threadIdx.x;
    int wid = tid >> 5, lane = tid & 31;
    int g = lane >> 2, cc = lane & 3;
    int m0 = blockIdx.x * 128;
    int wm = wid & 1, wn = wid >> 1;

    float acc[4][4][4];
    #pragma unroll
    for (int i = 0; i < 4; i++)
        #pragma unroll
        for (int j = 0; j < 4; j++)
            #pragma unroll
            for (int t = 0; t < 4; t++) acc[i][j][t] = 0.0f;

    int r_ld = tid >> 3, c4_ld = tid & 7;
    uint32_t soff_base = ((uint32_t)r_ld * 32 + (((uint32_t)c4_ld * 4) ^ ((r_ld & 7) * 4))) * 4;

    auto issue = [&](int kc, int buf) {
        int k0 = kc * 32;
        #pragma unroll
        for (int i = 0; i < 4; i++) {
            int r = r_ld + i * 32;
            uint32_t soff = soff_base + (uint32_t)i * 4096;
            CP16(sb + buf * 16384 + soff, A + (size_t)(m0 + r) * 512 + k0 + c4_ld * 4);
            CP16(sb + 32768 + buf * 16384 + soff, W + (size_t)r * 512 + k0 + c4_ld * 4);
        }
        CP_COMMIT();
    };

    issue(0, 0);
    for (int kc = 0; kc < 16; kc++) {
        if (kc + 1 < 16) { issue(kc + 1, (kc + 1) & 1); CP_WAIT(1); }
        else             { CP_WAIT(0); }
        __syncthreads();
        mma_chunk(gsm + (kc & 1) * 4096, gsm + 8192 + (kc & 1) * 4096, acc, wm, wn, g, cc);
        __syncthreads();
    }

    #pragma unroll
    for (int mt = 0; mt < 4; mt++) {
        int r0 = m0 + wm * 64 + mt * 16 + g;
        #pragma unroll
        for (int nt = 0; nt < 4; nt++) {
            int cb = wn * 32 + nt * 8 + cc * 2;
            float2 bb = *reinterpret_cast<const float2*>(bias + cb);
            #pragma unroll
            for (int hrow = 0; hrow < 2; hrow++) {
                int row = r0 + hrow * 8;
                float2 r2 = *reinterpret_cast<const float2*>(res + (size_t)row * CD + cb);
                float2 o;
                o.x = acc[mt][nt][hrow * 2 + 0] + bb.x + r2.x;
                o.y = acc[mt][nt][hrow * 2 + 1] + bb.y + r2.y;
                *reinterpret_cast<float2*>(C + (size_t)row * CD + cb) = o;
            }
        }
    }
}

// ============ proj GEMM + residual + LN2 fused epilogue =====================
__global__ void __launch_bounds__(256, 2)
proj_gemm(const float* __restrict__ A, const float* __restrict__ W,
          const float* __restrict__ bias, const float* __restrict__ x,
          const float* __restrict__ n2g, const float* __restrict__ n2b) {
    extern __shared__ float gsm[];
    __shared__ float rs1[128];
    __shared__ float rs2[128];
    uint32_t sb = smem_u32(gsm);
    int tid = threadIdx.x;
    int wid = tid >> 5, lane = tid & 31;
    int g = lane >> 2, cc = lane & 3;
    int m0 = blockIdx.x * 128;
    int wm = wid & 1, wn = wid >> 1;

    float acc[4][4][4];
    #pragma unroll
    for (int i = 0; i < 4; i++)
        #pragma unroll
        for (int j = 0; j < 4; j++)
            #pragma unroll
            for (int t = 0; t < 4; t++) acc[i][j][t] = 0.0f;

    int r_ld = tid >> 3, c4_ld = tid & 7;
    uint32_t soff_base = ((uint32_t)r_ld * 32 + (((uint32_t)c4_ld * 4) ^ ((r_ld & 7) * 4))) * 4;

    auto issue = [&](int kc, int buf) {
        int k0 = kc * 32;
        #pragma unroll
        for (int i = 0; i < 4; i++) {
            int r = r_ld + i * 32;
            uint32_t soff = soff_base + (uint32_t)i * 4096;
            CP16(sb + buf * 16384 + soff, A + (size_t)(m0 + r) * 128 + k0 + c4_ld * 4);
            CP16(sb + 32768 + buf * 16384 + soff, W + (size_t)r * 128 + k0 + c4_ld * 4);
        }
        CP_COMMIT();
    };

    if (tid < 128) { rs1[tid] = 0.0f; rs2[tid] = 0.0f; }

    issue(0, 0);
    for (int kc = 0; kc < 4; kc++) {
        if (kc + 1 < 4) { issue(kc + 1, (kc + 1) & 1); CP_WAIT(1); }
        else            { CP_WAIT(0); }
        __syncthreads();
        mma_chunk(gsm + (kc & 1) * 4096, gsm + 8192 + (kc & 1) * 4096, acc, wm, wn, g, cc);
        __syncthreads();
    }

    int tsp[4][2];
    #pragma unroll
    for (int mt = 0; mt < 4; mt++) {
        int rl = wm * 64 + mt * 16 + g;
        tsp[mt][0] = win_to_spatial(m0 + rl);
        tsp[mt][1] = win_to_spatial(m0 + rl + 8);
    }

    #pragma unroll
    for (int mt = 0; mt < 4; mt++) {
        #pragma unroll
        for (int hrow = 0; hrow < 2; hrow++) {
            int rl = wm * 64 + mt * 16 + g + hrow * 8;
            float s1 = 0.0f, s2 = 0.0f;
            #pragma unroll
            for (int nt = 0; nt < 4; nt++) {
                int cb = wn * 32 + nt * 8 + cc * 2;
                float2 bb = *reinterpret_cast<const float2*>(bias + cb);
                float2 xv = *reinterpret_cast<const float2*>(x + (size_t)tsp[mt][hrow] * CD + cb);
                float v0 = acc[mt][nt][hrow * 2 + 0] + bb.x + xv.x;
                float v1 = acc[mt][nt][hrow * 2 + 1] + bb.y + xv.y;
                acc[mt][nt][hrow * 2 + 0] = v0;
                acc[mt][nt][hrow * 2 + 1] = v1;
                s1 += v0 + v1;
                s2 += v0 * v0 + v1 * v1;
            }
            atomicAdd(&rs1[rl], s1);
            atomicAdd(&rs2[rl], s2);
        }
    }
    __syncthreads();

    #pragma unroll
    for (int mt = 0; mt < 4; mt++) {
        #pragma unroll
        for (int hrow = 0; hrow < 2; hrow++) {
            int rl = wm * 64 + mt * 16 + g + hrow * 8;
            int t_sp = tsp[mt][hrow];
            float mean = rs1[rl] * (1.0f / 128.0f);
            float var  = rs2[rl] * (1.0f / 128.0f) - mean * mean;
            float inv  = rsqrtf(var + 1e-5f);
            #pragma unroll
            for (int nt = 0; nt < 4; nt++) {
                int cb = wn * 32 + nt * 8 + cc * 2;
                float v0 = acc[mt][nt][hrow * 2 + 0];
                float v1 = acc[mt][nt][hrow * 2 + 1];
                float2 gg = *reinterpret_cast<const float2*>(n2g + cb);
                float2 bv = *reinterpret_cast<const float2*>(n2b + cb);
                float2 x2o; x2o.x = v0; x2o.y = v1;
                *reinterpret_cast<float2*>(g_x2 + (size_t)t_sp * CD + cb) = x2o;
                float2 yo;
                yo.x = tf32r((v0 - mean) * inv * gg.x + bv.x);
                yo.y = tf32r((v1 - mean) * inv * gg.y + bv.y);
                *reinterpret_cast<float2*>(g_y + (size_t)t_sp * CD + cb) = yo;
            }
        }
    }
}

// ---------------- rel-pos bias materialization ----------------
__global__ void bias_kernel(const float* __restrict__ rel_bias) {
    int t = blockIdx.x * blockDim.x + threadIdx.x;
    if (t >= NHEAD * NL * NL) return;
    int h = t / (NL * NL);
    int r = t % (NL * NL);
    int n = r / NL, m = r % NL;
    int id = n / 49, ih = (n / 7) % 7, iw = n % 7;
    int jd = m / 49, jh = (m / 7) % 7, jw = m % 7;
    int ridx = (id - jd + 1) * 169 + (ih - jh + 6) * 13 + (iw - jw + 6);
    g_bias[t] = rel_bias[ridx * NHEAD + h];
}

// ---------------- flash-style register attention ----------------
__global__ void __launch_bounds__(224, 2)
attn_flash(const float* __restrict__ mask) {
    __shared__ float Qs[112 * 32];
    __shared__ float Ks[104 * 32];
    __shared__ float Vs[104 * 32];
    int win = blockIdx.x, h = blockIdx.y;
    int tid = threadIdx.x, wid = tid >> 5, lane = tid & 31;
    int g = lane >> 2, cc = lane & 3;

    for (int i = tid; i < 14 * 32; i += 224) Qs[98 * 32 + i] = 0.0f;
    if (tid < 192) { Ks[98 * 32 + tid] = 0.0f; Vs[98 * 32 + tid] = 0.0f; }
    const float* base = g_qkv + (size_t)win * NL * 384 + h * 32;
    for (int e = tid; e < 98 * 24; e += 224) {
        int tok = e / 24, p = e - tok * 24;
        int which = p >> 3, c4 = p & 7;
        float4 v = *reinterpret_cast<const float4*>(base + (size_t)tok * 384 + which * 128 + c4 * 4);
        if (which == 0) {
            const float sc = 0.17677669529663689f;
            v.x *= sc; v.y *= sc; v.z *= sc; v.w *= sc;
        }
        float4 t;
        t.x = tf32r(v.x); t.y = tf32r(v.y); t.z = tf32r(v.z); t.w = tf32r(v.w);
        int col = (c4 * 4) ^ ((tok & 7) * 4);
        float* dst = (which == 0 ? Qs : which == 1 ? Ks : Vs) + tok * 32 + col;
        *reinterpret_cast<float4*>(dst) = t;
    }
    __syncthreads();

    int m0 = wid * 16;
    int r0 = m0 + g, r1 = m0 + g + 8;
    int sw = g * 4;

    uint32_t aq[4][4];
    #pragma unroll
    for (int kc = 0; kc < 4; kc++) {
        int col0 = (kc * 8 + cc) ^ sw;
        int col1 = (kc * 8 + cc + 4) ^ sw;
        aq[kc][0] = __float_as_uint(Qs[r0 * 32 + col0]);
        aq[kc][1] = __float_as_uint(Qs[r1 * 32 + col0]);
        aq[kc][2] = __float_as_uint(Qs[r0 * 32 + col1]);
        aq[kc][3] = __float_as_uint(Qs[r1 * 32 + col1]);
    }

    float sacc[13][4];
    #pragma unroll
    for (int nt = 0; nt < 13; nt++) {
        float s[4] = {0.f, 0.f, 0.f, 0.f};
        int nr = nt * 8 + g;
        #pragma unroll
        for (int kc = 0; kc < 4; kc++) {
            int col0 = (kc * 8 + cc) ^ sw;
            int col1 = (kc * 8 + cc + 4) ^ sw;
            uint32_t b0 = __float_as_uint(Ks[nr * 32 + col0]);
            uint32_t b1 = __float_as_uint(Ks[nr * 32 + col1]);
            mma_tf32(s, aq[kc][0], aq[kc][1], aq[kc][2], aq[kc][3], b0, b1);
        }
        sacc[nt][0] = s[0]; sacc[nt][1] = s[1]; sacc[nt][2] = s[2]; sacc[nt][3] = s[3];
    }

    {
        const float* bm = g_bias + (size_t)h * (NL * NL);
        const float* mk = mask + (size_t)(win & 255) * (NL * NL);
        int rc0 = (r0 < 98 ? r0 : 97) * 98;
        int rc1 = (r1 < 98 ? r1 : 97) * 98;
        #pragma unroll
        for (int nt = 0; nt < 13; nt++) {
            int col = nt * 8 + 2 * cc;
            if (col < 98) {
                sacc[nt][0] += __ldg(bm + rc0 + col) + __ldg(mk + rc0 + col);
                sacc[nt][2] += __ldg(bm + rc1 + col) + __ldg(mk + rc1 + col);
            } else { sacc[nt][0] = -1.0e38f; sacc[nt][2] = -1.0e38f; }
            if (col + 1 < 98) {
                sacc[nt][1] += __ldg(bm + rc0 + col + 1) + __ldg(mk + rc0 + col + 1);
                sacc[nt][3] += __ldg(bm + rc1 + col + 1) + __ldg(mk + rc1 + col + 1);
            } else { sacc[nt][1] = -1.0e38f; sacc[nt][3] = -1.0e38f; }
        }
    }

    float mx0 = -1.0e38f, mx1 = -1.0e38f;
    #pragma unroll
    for (int nt = 0; nt < 13; nt++) {
        mx0 = fmaxf(mx0, fmaxf(sacc[nt][0], sacc[nt][1]));
        mx1 = fmaxf(mx1, fmaxf(sacc[nt][2], sacc[nt][3]));
    }
    mx0 = fmaxf(mx0, __shfl_xor_sync(0xffffffffu, mx0, 1));
    mx0 = fmaxf(mx0, __shfl_xor_sync(0xffffffffu, mx0, 2));
    mx1 = fmaxf(mx1, __shfl_xor_sync(0xffffffffu, mx1, 1));
    mx1 = fmaxf(mx1, __shfl_xor_sync(0xffffffffu, mx1, 2));
    float sm0 = 0.f, sm1 = 0.f;
    #pragma unroll
    for (int nt = 0; nt < 13; nt++) {
        sacc[nt][0] = __expf(sacc[nt][0] - mx0);
        sacc[nt][1] = __expf(sacc[nt][1] - mx0);
        sacc[nt][2] = __expf(sacc[nt][2] - mx1);
        sacc[nt][3] = __expf(sacc[nt][3] - mx1);
        sm0 += sacc[nt][0] + sacc[nt][1];
        sm1 += sacc[nt][2] + sacc[nt][3];
    }
    sm0 += __shfl_xor_sync(0xffffffffu, sm0, 1);
    sm0 += __shfl_xor_sync(0xffffffffu, sm0, 2);
    sm1 += __shfl_xor_sync(0xffffffffu, sm1, 1);
    sm1 += __shfl_xor_sync(0xffffffffu, sm1, 2);
    float iv0 = 1.0f / sm0, iv1 = 1.0f / sm1;
    #pragma unroll
    for (int nt = 0; nt < 13; nt++) {
        sacc[nt][0] = tf32r(sacc[nt][0] * iv0);
        sacc[nt][1] = tf32r(sacc[nt][1] * iv0);
        sacc[nt][2] = tf32r(sacc[nt][2] * iv1);
        sacc[nt][3] = tf32r(sacc[nt][3] * iv1);
    }

    float oacc[4][4];
    #pragma unroll
    for (int vt = 0; vt < 4; vt++)
        #pragma unroll
        for (int t = 0; t < 4; t++) oacc[vt][t] = 0.0f;
    int qb = lane & ~3;
    int src0 = qb + (cc >> 1);
    bool odd = (cc & 1);
    #pragma unroll
    for (int kc = 0; kc < 13; kc++) {
        float p0 = sacc[kc][0], p1 = sacc[kc][1], p2 = sacc[kc][2], p3 = sacc[kc][3];
        float t0 = __shfl_sync(0xffffffffu, p0, src0);
        float t1 = __shfl_sync(0xffffffffu, p1, src0);
        float u0 = __shfl_sync(0xffffffffu, p0, src0 + 2);
        float u1 = __shfl_sync(0xffffffffu, p1, src0 + 2);
        float t2 = __shfl_sync(0xffffffffu, p2, src0);
        float t3 = __shfl_sync(0xffffffffu, p3, src0);
        float u2 = __shfl_sync(0xffffffffu, p2, src0 + 2);
        float u3 = __shfl_sync(0xffffffffu, p3, src0 + 2);
        uint32_t a0 = __float_as_uint(odd ? t1 : t0);
        uint32_t a2 = __float_as_uint(odd ? u1 : u0);
        uint32_t a1 = __float_as_uint(odd ? t3 : t2);
        uint32_t a3 = __float_as_uint(odd ? u3 : u2);
        int k0 = kc * 8;
        #pragma unroll
        for (int vt = 0; vt < 4; vt++) {
            uint32_t b0 = __float_as_uint(Vs[(k0 + cc) * 32     + ((vt * 8 + g) ^ (cc * 4))]);
            uint32_t b1 = __float_as_uint(Vs[(k0 + cc + 4) * 32 + ((vt * 8 + g) ^ (cc * 4 + 16))]);
            mma_tf32(oacc[vt], a0, a1, a2, a3, b0, b1);
        }
    }

    float* ob = g_attn + (size_t)win * NL * CD + h * 32;
    #pragma unroll
    for (int vt = 0; vt < 4; vt++) {
        int cb = vt * 8 + 2 * cc;
        if (r0 < NL) {
            float2 o; o.x = tf32r(oacc[vt][0]); o.y = tf32r(oacc[vt][1]);
            *reinterpret_cast<float2*>(ob + (size_t)r0 * CD + cb) = o;
        }
        if (r1 < NL) {
            float2 o; o.x = tf32r(oacc[vt][2]); o.y = tf32r(oacc[vt][3]);
            *reinterpret_cast<float2*>(ob + (size_t)r1 * CD + cb) = o;
        }
    }
}

// ---------------- launch ----------------
extern "C" void kernel_launch(void* const* d_in, const int* in_sizes, int n_in,
                              void* d_out, int out_size) {
    const float* x     = (const float*)d_in[0];
    const float* mask  = (const float*)d_in[1];
    const float* n1g   = (const float*)d_in[2];
    const float* n1b   = (const float*)d_in[3];
    const float* qkvw  = (const float*)d_in[4];
    const float* qkvb  = (const float*)d_in[5];
    const float* relb  = (const float*)d_in[6];
    const float* projw = (const float*)d_in[7];
    const float* projb = (const float*)d_in[8];
    const float* n2g   = (const float*)d_in[9];
    const float* n2b   = (const float*)d_in[10];
    const float* fc1w  = (const float*)d_in[11];
    const float* fc1b  = (const float*)d_in[12];
    const float* fc2w  = (const float*)d_in[13];
    const float* fc2b  = (const float*)d_in[14];
    float* out = (float*)d_out;

    void *p_qkv, *p_attn, *p_x2, *p_hid, *p_w;
    cudaGetSymbolAddress(&p_qkv,  g_qkv);
    cudaGetSymbolAddress(&p_attn, g_attn);
    cudaGetSymbolAddress(&p_x2,   g_x2);
    cudaGetSymbolAddress(&p_hid,  g_hid);
    cudaGetSymbolAddress(&p_w,    g_wcvt);
    float* wc = (float*)p_w;

    cudaFuncSetAttribute(qkv_ln_gemm, cudaFuncAttributeMaxDynamicSharedMemorySize, GEMM_SMEM_AR);
    cudaFuncSetAttribute(fc1_gemm,    cudaFuncAttributeMaxDynamicSharedMemorySize, GEMM_SMEM_AR);
    cudaFuncSetAttribute(fc2_gemm,    cudaFuncAttributeMaxDynamicSharedMemorySize, GEMM_SMEM_DB);
    cudaFuncSetAttribute(proj_gemm,   cudaFuncAttributeMaxDynamicSharedMemorySize, GEMM_SMEM_DB);

    cvt_kernel<<<(49152 + 255) / 256, 256>>>(qkvw, wc + W_QKV, 49152);
    cvt_kernel<<<(16384 + 255) / 256, 256>>>(projw, wc + W_PROJ, 16384);
    cvt_kernel<<<(65536 + 255) / 256, 256>>>(fc1w, wc + W_FC1, 65536);
    cvt_kernel<<<(65536 + 255) / 256, 256>>>(fc2w, wc + W_FC2, 65536);
    bias_kernel<<<(NHEAD * NL * NL + 255) / 256, 256>>>(relb);

    // fused LN1 + QKV gemm
    qkv_ln_gemm<<<TOKENS / 128, 256, GEMM_SMEM_AR>>>(
        x, n1g, n1b, wc + W_QKV, qkvb, (float*)p_qkv);
    attn_flash<<<dim3(NWIN, NHEAD), 224>>>(mask);
    proj_gemm<<<TOKENS / 128, 256, GEMM_SMEM_DB>>>(
        (const float*)p_attn, wc + W_PROJ, projb, x, n2g, n2b);
    fc1_gemm<<<TOKENS / 128, 256, GEMM_SMEM_AR>>>(
        wc + W_FC1, fc1b, (float*)p_hid);
    fc2_gemm<<<TOKENS / 128, 256, GEMM_SMEM_DB>>>(
        (const float*)p_hid, wc + W_FC2, fc2b, (const float*)p_x2, out);
}

// round 11
// speedup vs baseline: 1.1982x; 1.0985x over previous
#include <cuda_runtime.h>
#include <math.h>
#include <stdint.h>

// ---------------- problem constants ----------------
#define TOKENS 200704          // 8*8*56*56
#define CD     128
#define NWIN   2048
#define NL     98
#define NHEAD  4

#define SMEM_AR3 (114688)   // A-resident: 64KB A + 3x16KB W stages
#define SMEM_3S  (98304)    // streaming: 3 stages x (16KB A + 16KB W)

// weight cvt offsets (floats)
#define W_QKV  0
#define W_PROJ 49152
#define W_FC1  65536
#define W_FC2  131072
#define W_TOT  196608

// ---------------- scratch ----------------
__device__ float g_qkv [(size_t)TOKENS * 3 * CD];
__device__ float g_bias[(size_t)NHEAD * NL * NL];
__device__ float g_attn[(size_t)TOKENS * CD];
__device__ float g_x2  [(size_t)TOKENS * CD];
__device__ float g_y   [(size_t)TOKENS * CD];
__device__ float g_hid [(size_t)TOKENS * 4 * CD];
__device__ float g_wcvt[W_TOT];

// ---------------- helpers ----------------
__device__ __forceinline__ float tf32r(float v) {
    uint32_t o;
    asm("cvt.rna.tf32.f32 %0, %1;" : "=r"(o) : "f"(v));
    return __uint_as_float(o);
}
__device__ __forceinline__ void mma_tf32(float c[4],
                                         uint32_t a0, uint32_t a1, uint32_t a2, uint32_t a3,
                                         uint32_t b0, uint32_t b1) {
    asm volatile(
        "mma.sync.aligned.m16n8k8.row.col.f32.tf32.tf32.f32 "
        "{%0,%1,%2,%3}, {%4,%5,%6,%7}, {%8,%9}, {%0,%1,%2,%3};\n"
        : "+f"(c[0]), "+f"(c[1]), "+f"(c[2]), "+f"(c[3])
        : "r"(a0), "r"(a1), "r"(a2), "r"(a3), "r"(b0), "r"(b1));
}
__device__ __forceinline__ uint32_t smem_u32(const void* p) {
    uint32_t a;
    asm("{ .reg .u64 t; cvta.to.shared.u64 t, %1; cvt.u32.u64 %0, t; }" : "=r"(a) : "l"(p));
    return a;
}
#define CP16(dst, src) \
    asm volatile("cp.async.cg.shared.global [%0], [%1], 16;\n" :: "r"(dst), "l"(src))
#define CP_COMMIT() asm volatile("cp.async.commit_group;\n" ::: "memory")
#define CP_WAIT(n)  asm volatile("cp.async.wait_group %0;\n" :: "n"(n) : "memory")

// one 128x128x32 mma sub-block
__device__ __forceinline__ void mma_chunk(const float* __restrict__ Ab,
                                          const float* __restrict__ Bb,
                                          float (*acc)[4][4],
                                          int wm, int wn, int g, int cc) {
    #pragma unroll
    for (int ks = 0; ks < 4; ks++) {
        int k0 = ks * 8;
        int sw = g * 4;
        uint32_t af[4][4];
        #pragma unroll
        for (int mt = 0; mt < 4; mt++) {
            int rb = wm * 64 + mt * 16 + g;
            af[mt][0] = __float_as_uint(Ab[rb * 32       + ((k0 + cc)     ^ sw)]);
            af[mt][1] = __float_as_uint(Ab[(rb + 8) * 32 + ((k0 + cc)     ^ sw)]);
            af[mt][2] = __float_as_uint(Ab[rb * 32       + ((k0 + cc + 4) ^ sw)]);
            af[mt][3] = __float_as_uint(Ab[(rb + 8) * 32 + ((k0 + cc + 4) ^ sw)]);
        }
        uint32_t bf[4][2];
        #pragma unroll
        for (int nt = 0; nt < 4; nt++) {
            int nb = wn * 32 + nt * 8 + g;
            bf[nt][0] = __float_as_uint(Bb[nb * 32 + ((k0 + cc)     ^ sw)]);
            bf[nt][1] = __float_as_uint(Bb[nb * 32 + ((k0 + cc + 4) ^ sw)]);
        }
        #pragma unroll
        for (int mt = 0; mt < 4; mt++)
            #pragma unroll
            for (int nt = 0; nt < 4; nt++)
                mma_tf32(acc[mt][nt], af[mt][0], af[mt][1], af[mt][2], af[mt][3],
                         bf[nt][0], bf[nt][1]);
    }
}

// window row -> spatial token
__device__ __forceinline__ int win_to_spatial(int gr) {
    int win = gr / NL, n = gr % NL;
    int bb = win >> 8, wl = win & 255;
    int dz = wl >> 6, hy = (wl >> 3) & 7, wx = wl & 7;
    int id = n / 49, ih = (n / 7) % 7, iw = n % 7;
    int d  = (dz * 2 + id + 1) & 7;
    int hh = hy * 7 + ih + 3; if (hh >= 56) hh -= 56;
    int ww = wx * 7 + iw + 3; if (ww >= 56) ww -= 56;
    return ((bb * 8 + d) * 56 + hh) * 56 + ww;
}

// ---------------- merged prep: weight tf32 cvt + rel-pos bias ----------------
__global__ void prep_kernel(const float* __restrict__ qkvw, const float* __restrict__ projw,
                            const float* __restrict__ fc1w, const float* __restrict__ fc2w,
                            const float* __restrict__ rel_bias) {
    int i = blockIdx.x * 256 + threadIdx.x;
    if (i < 49152)       g_wcvt[i] = tf32r(qkvw[i]);
    else if (i < 65536)  g_wcvt[i] = tf32r(projw[i - 49152]);
    else if (i < 131072) g_wcvt[i] = tf32r(fc1w[i - 65536]);
    else if (i < 196608) g_wcvt[i] = tf32r(fc2w[i - 131072]);
    else {
        int t = i - 196608;
        if (t >= NHEAD * NL * NL) return;
        int h = t / (NL * NL);
        int r = t % (NL * NL);
        int n = r / NL, m = r % NL;
        int id = n / 49, ih = (n / 7) % 7, iw = n % 7;
        int jd = m / 49, jh = (m / 7) % 7, jw = m % 7;
        int ridx = (id - jd + 1) * 169 + (ih - jh + 6) * 13 + (iw - jw + 6);
        g_bias[t] = rel_bias[ridx * NHEAD + h];
    }
}

// ============ QKV: fused LN1-gather + A-resident, continuous 12-chunk W pipe
__global__ void __launch_bounds__(256, 2)
qkv_ln_gemm(const float* __restrict__ x,
            const float* __restrict__ n1g, const float* __restrict__ n1b,
            const float* __restrict__ W, const float* __restrict__ bias,
            float* __restrict__ C) {
    extern __shared__ float gsm[];
    uint32_t sb = smem_u32(gsm);
    const uint32_t WOFFB = 65536u;          // bytes; floats: 16384
    int tid = threadIdx.x;
    int wid = tid >> 5, lane = tid & 31;
    int g = lane >> 2, cc = lane & 3;
    int m0 = blockIdx.x * 128;
    int wm = wid & 1, wn = wid >> 1;

    int r_ld = tid >> 3, c4_ld = tid & 7;
    uint32_t soff_base = ((uint32_t)r_ld * 32 + (((uint32_t)c4_ld * 4) ^ ((r_ld & 7) * 4))) * 4;

    // W chunk t: n0=(t>>2)*128 rows, k0=(t&3)*32 cols, buffer t%3
    auto issueW = [&](int t) {
        int n0 = (t >> 2) * 128, k0 = (t & 3) * 32;
        uint32_t dst = sb + WOFFB + (uint32_t)(t % 3) * 16384u;
        #pragma unroll
        for (int i = 0; i < 4; i++) {
            int r = r_ld + i * 32;
            CP16(dst + soff_base + (uint32_t)i * 4096,
                 W + (size_t)(n0 + r) * 128 + k0 + c4_ld * 4);
        }
        CP_COMMIT();
    };

    issueW(0);
    issueW(1);

    // ---- LN1 gather into A smem (overlaps W prefetch) ----
    {
        float4 gg = reinterpret_cast<const float4*>(n1g)[lane];
        float4 bv = reinterpret_cast<const float4*>(n1b)[lane];
        int cchunk = lane >> 3;
        int colbase = (lane * 4) & 31;
        for (int r = wid; r < 128; r += 8) {
            int src = win_to_spatial(m0 + r);
            float4 v = reinterpret_cast<const float4*>(x + (size_t)src * CD)[lane];
            float s1 = v.x + v.y + v.z + v.w;
            float s2 = v.x*v.x + v.y*v.y + v.z*v.z + v.w*v.w;
            #pragma unroll
            for (int o = 16; o; o >>= 1) {
                s1 += __shfl_xor_sync(0xffffffffu, s1, o);
                s2 += __shfl_xor_sync(0xffffffffu, s2, o);
            }
            float mean = s1 * (1.0f / 128.0f);
            float var  = s2 * (1.0f / 128.0f) - mean * mean;
            float inv  = rsqrtf(var + 1e-5f);
            float4 o;
            o.x = tf32r((v.x - mean) * inv * gg.x + bv.x);
            o.y = tf32r((v.y - mean) * inv * gg.y + bv.y);
            o.z = tf32r((v.z - mean) * inv * gg.z + bv.z);
            o.w = tf32r((v.w - mean) * inv * gg.w + bv.w);
            int col = colbase ^ ((r & 7) * 4);
            *reinterpret_cast<float4*>(gsm + cchunk * 4096 + r * 32 + col) = o;
        }
    }

    float acc[4][4][4];
    for (int t = 0; t < 12; t++) {
        if (t + 1 < 12) CP_WAIT(1); else CP_WAIT(0);
        __syncthreads();
        if ((t & 3) == 0) {
            #pragma unroll
            for (int i = 0; i < 4; i++)
                #pragma unroll
                for (int j = 0; j < 4; j++)
                    #pragma unroll
                    for (int q = 0; q < 4; q++) acc[i][j][q] = 0.0f;
        }
        mma_chunk(gsm + (t & 3) * 4096, gsm + 16384 + (t % 3) * 4096, acc, wm, wn, g, cc);
        if (t + 2 < 12) issueW(t + 2);
        if ((t & 3) == 3) {
            int n0 = (t >> 2) * 128;
            #pragma unroll
            for (int mt = 0; mt < 4; mt++) {
                int r0 = m0 + wm * 64 + mt * 16 + g;
                #pragma unroll
                for (int nt = 0; nt < 4; nt++) {
                    int cb = n0 + wn * 32 + nt * 8 + cc * 2;
                    float2 bb = *reinterpret_cast<const float2*>(bias + cb);
                    #pragma unroll
                    for (int hrow = 0; hrow < 2; hrow++) {
                        int row = r0 + hrow * 8;
                        float2 o;
                        o.x = acc[mt][nt][hrow * 2 + 0] + bb.x;
                        o.y = acc[mt][nt][hrow * 2 + 1] + bb.y;
                        *reinterpret_cast<float2*>(C + (size_t)row * 384 + cb) = o;
                    }
                }
            }
        }
    }
}

// ============ fc1: A-resident, continuous 16-chunk W pipe, GELU epilogue ====
__global__ void __launch_bounds__(256, 2)
fc1_gemm(const float* __restrict__ W, const float* __restrict__ bias,
         float* __restrict__ C) {
    extern __shared__ float gsm[];
    uint32_t sb = smem_u32(gsm);
    const uint32_t WOFFB = 65536u;
    int tid = threadIdx.x;
    int wid = tid >> 5, lane = tid & 31;
    int g = lane >> 2, cc = lane & 3;
    int m0 = blockIdx.x * 128;
    int wm = wid & 1, wn = wid >> 1;

    int r_ld = tid >> 3, c4_ld = tid & 7;
    uint32_t soff_base = ((uint32_t)r_ld * 32 + (((uint32_t)c4_ld * 4) ^ ((r_ld & 7) * 4))) * 4;

    // group 0: full A tile (g_y already tf32)
    #pragma unroll
    for (int c = 0; c < 4; c++) {
        #pragma unroll
        for (int i = 0; i < 4; i++) {
            int r = r_ld + i * 32;
            CP16(sb + (uint32_t)c * 16384 + soff_base + (uint32_t)i * 4096,
                 g_y + (size_t)(m0 + r) * 128 + c * 32 + c4_ld * 4);
        }
    }
    CP_COMMIT();

    auto issueW = [&](int t) {
        int n0 = (t >> 2) * 128, k0 = (t & 3) * 32;
        uint32_t dst = sb + WOFFB + (uint32_t)(t % 3) * 16384u;
        #pragma unroll
        for (int i = 0; i < 4; i++) {
            int r = r_ld + i * 32;
            CP16(dst + soff_base + (uint32_t)i * 4096,
                 W + (size_t)(n0 + r) * 128 + k0 + c4_ld * 4);
        }
        CP_COMMIT();
    };

    issueW(0);
    issueW(1);

    float acc[4][4][4];
    for (int t = 0; t < 16; t++) {
        if (t + 1 < 16) CP_WAIT(1); else CP_WAIT(0);
        __syncthreads();
        if ((t & 3) == 0) {
            #pragma unroll
            for (int i = 0; i < 4; i++)
                #pragma unroll
                for (int j = 0; j < 4; j++)
                    #pragma unroll
                    for (int q = 0; q < 4; q++) acc[i][j][q] = 0.0f;
        }
        mma_chunk(gsm + (t & 3) * 4096, gsm + 16384 + (t % 3) * 4096, acc, wm, wn, g, cc);
        if (t + 2 < 16) issueW(t + 2);
        if ((t & 3) == 3) {
            int n0 = (t >> 2) * 128;
            #pragma unroll
            for (int mt = 0; mt < 4; mt++) {
                int r0 = m0 + wm * 64 + mt * 16 + g;
                #pragma unroll
                for (int nt = 0; nt < 4; nt++) {
                    int cb = n0 + wn * 32 + nt * 8 + cc * 2;
                    float2 bb = *reinterpret_cast<const float2*>(bias + cb);
                    #pragma unroll
                    for (int hrow = 0; hrow < 2; hrow++) {
                        int row = r0 + hrow * 8;
                        float v0 = acc[mt][nt][hrow * 2 + 0] + bb.x;
                        float v1 = acc[mt][nt][hrow * 2 + 1] + bb.y;
                        v0 = tf32r(0.5f * v0 * (1.0f + erff(v0 * 0.70710678118654752f)));
                        v1 = tf32r(0.5f * v1 * (1.0f + erff(v1 * 0.70710678118654752f)));
                        float2 o; o.x = v0; o.y = v1;
                        *reinterpret_cast<float2*>(C + (size_t)row * 512 + cb) = o;
                    }
                }
            }
        }
    }
}

// ============ fc2: streaming 3-stage, +bias +residual ======================
__global__ void __launch_bounds__(256, 2)
fc2_gemm(const float* __restrict__ A, const float* __restrict__ W,
         const float* __restrict__ bias, const float* __restrict__ res,
         float* __restrict__ C) {
    extern __shared__ float gsm[];
    uint32_t sb = smem_u32(gsm);
    int tid = threadIdx.x;
    int wid = tid >> 5, lane = tid & 31;
    int g = lane >> 2, cc = lane & 3;
    int m0 = blockIdx.x * 128;
    int wm = wid & 1, wn = wid >> 1;

    float acc[4][4][4];
    #pragma unroll
    for (int i = 0; i < 4; i++)
        #pragma unroll
        for (int j = 0; j < 4; j++)
            #pragma unroll
            for (int t = 0; t < 4; t++) acc[i][j][t] = 0.0f;

    int r_ld = tid >> 3, c4_ld = tid & 7;
    uint32_t soff_base = ((uint32_t)r_ld * 32 + (((uint32_t)c4_ld * 4) ^ ((r_ld & 7) * 4))) * 4;

    // stage s: A at s*32768, W at s*32768+16384 (bytes)
    auto issue = [&](int kc) {
        int k0 = kc * 32;
        uint32_t st = sb + (uint32_t)(kc % 3) * 32768u;
        #pragma unroll
        for (int i = 0; i < 4; i++) {
            int r = r_ld + i * 32;
            uint32_t soff = soff_base + (uint32_t)i * 4096;
            CP16(st + soff, A + (size_t)(m0 + r) * 512 + k0 + c4_ld * 4);
            CP16(st + 16384u + soff, W + (size_t)r * 512 + k0 + c4_ld * 4);
        }
        CP_COMMIT();
    };

    issue(0);
    issue(1);
    for (int kc = 0; kc < 16; kc++) {
        if (kc + 1 < 16) CP_WAIT(1); else CP_WAIT(0);
        __syncthreads();
        const float* st = gsm + (kc % 3) * 8192;
        mma_chunk(st, st + 4096, acc, wm, wn, g, cc);
        if (kc + 2 < 16) issue(kc + 2);
    }

    #pragma unroll
    for (int mt = 0; mt < 4; mt++) {
        int r0 = m0 + wm * 64 + mt * 16 + g;
        #pragma unroll
        for (int nt = 0; nt < 4; nt++) {
            int cb = wn * 32 + nt * 8 + cc * 2;
            float2 bb = *reinterpret_cast<const float2*>(bias + cb);
            #pragma unroll
            for (int hrow = 0; hrow < 2; hrow++) {
                int row = r0 + hrow * 8;
                float2 r2 = *reinterpret_cast<const float2*>(res + (size_t)row * CD + cb);
                float2 o;
                o.x = acc[mt][nt][hrow * 2 + 0] + bb.x + r2.x;
                o.y = acc[mt][nt][hrow * 2 + 1] + bb.y + r2.y;
                *reinterpret_cast<float2*>(C + (size_t)row * CD + cb) = o;
            }
        }
    }
}

// ============ proj: streaming 3-stage + residual + LN2 fused epilogue =======
__global__ void __launch_bounds__(256, 2)
proj_gemm(const float* __restrict__ A, const float* __restrict__ W,
          const float* __restrict__ bias, const float* __restrict__ x,
          const float* __restrict__ n2g, const float* __restrict__ n2b) {
    extern __shared__ float gsm[];
    __shared__ float rs1[128];
    __shared__ float rs2[128];
    uint32_t sb = smem_u32(gsm);
    int tid = threadIdx.x;
    int wid = tid >> 5, lane = tid & 31;
    int g = lane >> 2, cc = lane & 3;
    int m0 = blockIdx.x * 128;
    int wm = wid & 1, wn = wid >> 1;

    float acc[4][4][4];
    #pragma unroll
    for (int i = 0; i < 4; i++)
        #pragma unroll
        for (int j = 0; j < 4; j++)
            #pragma unroll
            for (int t = 0; t < 4; t++) acc[i][j][t] = 0.0f;

    int r_ld = tid >> 3, c4_ld = tid & 7;
    uint32_t soff_base = ((uint32_t)r_ld * 32 + (((uint32_t)c4_ld * 4) ^ ((r_ld & 7) * 4))) * 4;

    auto issue = [&](int kc) {
        int k0 = kc * 32;
        uint32_t st = sb + (uint32_t)(kc % 3) * 32768u;
        #pragma unroll
        for (int i = 0; i < 4; i++) {
            int r = r_ld + i * 32;
            uint32_t soff = soff_base + (uint32_t)i * 4096;
            CP16(st + soff, A + (size_t)(m0 + r) * 128 + k0 + c4_ld * 4);
            CP16(st + 16384u + soff, W + (size_t)r * 128 + k0 + c4_ld * 4);
        }
        CP_COMMIT();
    };

    if (tid < 128) { rs1[tid] = 0.0f; rs2[tid] = 0.0f; }

    issue(0);
    issue(1);
    for (int kc = 0; kc < 4; kc++) {
        if (kc + 1 < 4) CP_WAIT(1); else CP_WAIT(0);
        __syncthreads();
        const float* st = gsm + (kc % 3) * 8192;
        mma_chunk(st, st + 4096, acc, wm, wn, g, cc);
        if (kc + 2 < 4) issue(kc + 2);
    }

    int tsp[4][2];
    #pragma unroll
    for (int mt = 0; mt < 4; mt++) {
        int rl = wm * 64 + mt * 16 + g;
        tsp[mt][0] = win_to_spatial(m0 + rl);
        tsp[mt][1] = win_to_spatial(m0 + rl + 8);
    }

    #pragma unroll
    for (int mt = 0; mt < 4; mt++) {
        #pragma unroll
        for (int hrow = 0; hrow < 2; hrow++) {
            int rl = wm * 64 + mt * 16 + g + hrow * 8;
            float s1 = 0.0f, s2 = 0.0f;
            #pragma unroll
            for (int nt = 0; nt < 4; nt++) {
                int cb = wn * 32 + nt * 8 + cc * 2;
                float2 bb = *reinterpret_cast<const float2*>(bias + cb);
                float2 xv = *reinterpret_cast<const float2*>(x + (size_t)tsp[mt][hrow] * CD + cb);
                float v0 = acc[mt][nt][hrow * 2 + 0] + bb.x + xv.x;
                float v1 = acc[mt][nt][hrow * 2 + 1] + bb.y + xv.y;
                acc[mt][nt][hrow * 2 + 0] = v0;
                acc[mt][nt][hrow * 2 + 1] = v1;
                s1 += v0 + v1;
                s2 += v0 * v0 + v1 * v1;
            }
            atomicAdd(&rs1[rl], s1);
            atomicAdd(&rs2[rl], s2);
        }
    }
    __syncthreads();

    #pragma unroll
    for (int mt = 0; mt < 4; mt++) {
        #pragma unroll
        for (int hrow = 0; hrow < 2; hrow++) {
            int rl = wm * 64 + mt * 16 + g + hrow * 8;
            int t_sp = tsp[mt][hrow];
            float mean = rs1[rl] * (1.0f / 128.0f);
            float var  = rs2[rl] * (1.0f / 128.0f) - mean * mean;
            float inv  = rsqrtf(var + 1e-5f);
            #pragma unroll
            for (int nt = 0; nt < 4; nt++) {
                int cb = wn * 32 + nt * 8 + cc * 2;
                float v0 = acc[mt][nt][hrow * 2 + 0];
                float v1 = acc[mt][nt][hrow * 2 + 1];
                float2 gg = *reinterpret_cast<const float2*>(n2g + cb);
                float2 bv = *reinterpret_cast<const float2*>(n2b + cb);
                float2 x2o; x2o.x = v0; x2o.y = v1;
                *reinterpret_cast<float2*>(g_x2 + (size_t)t_sp * CD + cb) = x2o;
                float2 yo;
                yo.x = tf32r((v0 - mean) * inv * gg.x + bv.x);
                yo.y = tf32r((v1 - mean) * inv * gg.y + bv.y);
                *reinterpret_cast<float2*>(g_y + (size_t)t_sp * CD + cb) = yo;
            }
        }
    }
}

// ---------------- flash-style register attention ----------------
__global__ void __launch_bounds__(224, 3)
attn_flash(const float* __restrict__ mask) {
    __shared__ float Qs[112 * 32];
    __shared__ float Ks[104 * 32];
    __shared__ float Vs[104 * 32];
    int win = blockIdx.x, h = blockIdx.y;
    int tid = threadIdx.x, wid = tid >> 5, lane = tid & 31;
    int g = lane >> 2, cc = lane & 3;

    for (int i = tid; i < 14 * 32; i += 224) Qs[98 * 32 + i] = 0.0f;
    if (tid < 192) { Ks[98 * 32 + tid] = 0.0f; Vs[98 * 32 + tid] = 0.0f; }
    const float* base = g_qkv + (size_t)win * NL * 384 + h * 32;
    for (int e = tid; e < 98 * 24; e += 224) {
        int tok = e / 24, p = e - tok * 24;
        int which = p >> 3, c4 = p & 7;
        float4 v = *reinterpret_cast<const float4*>(base + (size_t)tok * 384 + which * 128 + c4 * 4);
        if (which == 0) {
            const float sc = 0.17677669529663689f;
            v.x *= sc; v.y *= sc; v.z *= sc; v.w *= sc;
        }
        float4 t;
        t.x = tf32r(v.x); t.y = tf32r(v.y); t.z = tf32r(v.z); t.w = tf32r(v.w);
        int col = (c4 * 4) ^ ((tok & 7) * 4);
        float* dst = (which == 0 ? Qs : which == 1 ? Ks : Vs) + tok * 32 + col;
        *reinterpret_cast<float4*>(dst) = t;
    }
    __syncthreads();

    int m0 = wid * 16;
    int r0 = m0 + g, r1 = m0 + g + 8;
    int sw = g * 4;

    uint32_t aq[4][4];
    #pragma unroll
    for (int kc = 0; kc < 4; kc++) {
        int col0 = (kc * 8 + cc) ^ sw;
        int col1 = (kc * 8 + cc + 4) ^ sw;
        aq[kc][0] = __float_as_uint(Qs[r0 * 32 + col0]);
        aq[kc][1] = __float_as_uint(Qs[r1 * 32 + col0]);
        aq[kc][2] = __float_as_uint(Qs[r0 * 32 + col1]);
        aq[kc][3] = __float_as_uint(Qs[r1 * 32 + col1]);
    }

    float sacc[13][4];
    #pragma unroll
    for (int nt = 0; nt < 13; nt++) {
        float s[4] = {0.f, 0.f, 0.f, 0.f};
        int nr = nt * 8 + g;
        #pragma unroll
        for (int kc = 0; kc < 4; kc++) {
            int col0 = (kc * 8 + cc) ^ sw;
            int col1 = (kc * 8 + cc + 4) ^ sw;
            uint32_t b0 = __float_as_uint(Ks[nr * 32 + col0]);
            uint32_t b1 = __float_as_uint(Ks[nr * 32 + col1]);
            mma_tf32(s, aq[kc][0], aq[kc][1], aq[kc][2], aq[kc][3], b0, b1);
        }
        sacc[nt][0] = s[0]; sacc[nt][1] = s[1]; sacc[nt][2] = s[2]; sacc[nt][3] = s[3];
    }

    {
        const float* bm = g_bias + (size_t)h * (NL * NL);
        const float* mk = mask + (size_t)(win & 255) * (NL * NL);
        int rc0 = (r0 < 98 ? r0 : 97) * 98;
        int rc1 = (r1 < 98 ? r1 : 97) * 98;
        #pragma unroll
        for (int nt = 0; nt < 13; nt++) {
            int col = nt * 8 + 2 * cc;
            if (col < 98) {
                sacc[nt][0] += __ldg(bm + rc0 + col) + __ldg(mk + rc0 + col);
                sacc[nt][2] += __ldg(bm + rc1 + col) + __ldg(mk + rc1 + col);
            } else { sacc[nt][0] = -1.0e38f; sacc[nt][2] = -1.0e38f; }
            if (col + 1 < 98) {
                sacc[nt][1] += __ldg(bm + rc0 + col + 1) + __ldg(mk + rc0 + col + 1);
                sacc[nt][3] += __ldg(bm + rc1 + col + 1) + __ldg(mk + rc1 + col + 1);
            } else { sacc[nt][1] = -1.0e38f; sacc[nt][3] = -1.0e38f; }
        }
    }

    float mx0 = -1.0e38f, mx1 = -1.0e38f;
    #pragma unroll
    for (int nt = 0; nt < 13; nt++) {
        mx0 = fmaxf(mx0, fmaxf(sacc[nt][0], sacc[nt][1]));
        mx1 = fmaxf(mx1, fmaxf(sacc[nt][2], sacc[nt][3]));
    }
    mx0 = fmaxf(mx0, __shfl_xor_sync(0xffffffffu, mx0, 1));
    mx0 = fmaxf(mx0, __shfl_xor_sync(0xffffffffu, mx0, 2));
    mx1 = fmaxf(mx1, __shfl_xor_sync(0xffffffffu, mx1, 1));
    mx1 = fmaxf(mx1, __shfl_xor_sync(0xffffffffu, mx1, 2));
    float sm0 = 0.f, sm1 = 0.f;
    #pragma unroll
    for (int nt = 0; nt < 13; nt++) {
        sacc[nt][0] = __expf(sacc[nt][0] - mx0);
        sacc[nt][1] = __expf(sacc[nt][1] - mx0);
        sacc[nt][2] = __expf(sacc[nt][2] - mx1);
        sacc[nt][3] = __expf(sacc[nt][3] - mx1);
        sm0 += sacc[nt][0] + sacc[nt][1];
        sm1 += sacc[nt][2] + sacc[nt][3];
    }
    sm0 += __shfl_xor_sync(0xffffffffu, sm0, 1);
    sm0 += __shfl_xor_sync(0xffffffffu, sm0, 2);
    sm1 += __shfl_xor_sync(0xffffffffu, sm1, 1);
    sm1 += __shfl_xor_sync(0xffffffffu, sm1, 2);
    float iv0 = 1.0f / sm0, iv1 = 1.0f / sm1;
    #pragma unroll
    for (int nt = 0; nt < 13; nt++) {
        sacc[nt][0] = tf32r(sacc[nt][0] * iv0);
        sacc[nt][1] = tf32r(sacc[nt][1] * iv0);
        sacc[nt][2] = tf32r(sacc[nt][2] * iv1);
        sacc[nt][3] = tf32r(sacc[nt][3] * iv1);
    }

    float oacc[4][4];
    #pragma unroll
    for (int vt = 0; vt < 4; vt++)
        #pragma unroll
        for (int t = 0; t < 4; t++) oacc[vt][t] = 0.0f;
    int qb = lane & ~3;
    int src0 = qb + (cc >> 1);
    bool odd = (cc & 1);
    #pragma unroll
    for (int kc = 0; kc < 13; kc++) {
        float p0 = sacc[kc][0], p1 = sacc[kc][1], p2 = sacc[kc][2], p3 = sacc[kc][3];
        float t0 = __shfl_sync(0xffffffffu, p0, src0);
        float t1 = __shfl_sync(0xffffffffu, p1, src0);
        float u0 = __shfl_sync(0xffffffffu, p0, src0 + 2);
        float u1 = __shfl_sync(0xffffffffu, p1, src0 + 2);
        float t2 = __shfl_sync(0xffffffffu, p2, src0);
        float t3 = __shfl_sync(0xffffffffu, p3, src0);
        float u2 = __shfl_sync(0xffffffffu, p2, src0 + 2);
        float u3 = __shfl_sync(0xffffffffu, p3, src0 + 2);
        uint32_t a0 = __float_as_uint(odd ? t1 : t0);
        uint32_t a2 = __float_as_uint(odd ? u1 : u0);
        uint32_t a1 = __float_as_uint(odd ? t3 : t2);
        uint32_t a3 = __float_as_uint(odd ? u3 : u2);
        int k0 = kc * 8;
        #pragma unroll
        for (int vt = 0; vt < 4; vt++) {
            uint32_t b0 = __float_as_uint(Vs[(k0 + cc) * 32     + ((vt * 8 + g) ^ (cc * 4))]);
            uint32_t b1 = __float_as_uint(Vs[(k0 + cc + 4) * 32 + ((vt * 8 + g) ^ (cc * 4 + 16))]);
            mma_tf32(oacc[vt], a0, a1, a2, a3, b0, b1);
        }
    }

    float* ob = g_attn + (size_t)win * NL * CD + h * 32;
    #pragma unroll
    for (int vt = 0; vt < 4; vt++) {
        int cb = vt * 8 + 2 * cc;
        if (r0 < NL) {
            float2 o; o.x = tf32r(oacc[vt][0]); o.y = tf32r(oacc[vt][1]);
            *reinterpret_cast<float2*>(ob + (size_t)r0 * CD + cb) = o;
        }
        if (r1 < NL) {
            float2 o; o.x = tf32r(oacc[vt][2]); o.y = tf32r(oacc[vt][3]);
            *reinterpret_cast<float2*>(ob + (size_t)r1 * CD + cb) = o;
        }
    }
}

// ---------------- launch ----------------
extern "C" void kernel_launch(void* const* d_in, const int* in_sizes, int n_in,
                              void* d_out, int out_size) {
    const float* x     = (const float*)d_in[0];
    const float* mask  = (const float*)d_in[1];
    const float* n1g   = (const float*)d_in[2];
    const float* n1b   = (const float*)d_in[3];
    const float* qkvw  = (const float*)d_in[4];
    const float* qkvb  = (const float*)d_in[5];
    const float* relb  = (const float*)d_in[6];
    const float* projw = (const float*)d_in[7];
    const float* projb = (const float*)d_in[8];
    const float* n2g   = (const float*)d_in[9];
    const float* n2b   = (const float*)d_in[10];
    const float* fc1w  = (const float*)d_in[11];
    const float* fc1b  = (const float*)d_in[12];
    const float* fc2w  = (const float*)d_in[13];
    const float* fc2b  = (const float*)d_in[14];
    float* out = (float*)d_out;

    void *p_qkv, *p_attn, *p_x2, *p_hid, *p_w;
    cudaGetSymbolAddress(&p_qkv,  g_qkv);
    cudaGetSymbolAddress(&p_attn, g_attn);
    cudaGetSymbolAddress(&p_x2,   g_x2);
    cudaGetSymbolAddress(&p_hid,  g_hid);
    cudaGetSymbolAddress(&p_w,    g_wcvt);
    float* wc = (float*)p_w;

    cudaFuncSetAttribute(qkv_ln_gemm, cudaFuncAttributeMaxDynamicSharedMemorySize, SMEM_AR3);
    cudaFuncSetAttribute(fc1_gemm,    cudaFuncAttributeMaxDynamicSharedMemorySize, SMEM_AR3);
    cudaFuncSetAttribute(fc2_gemm,    cudaFuncAttributeMaxDynamicSharedMemorySize, SMEM_3S);
    cudaFuncSetAttribute(proj_gemm,   cudaFuncAttributeMaxDynamicSharedMemorySize, SMEM_3S);

    // one merged prep launch (weights cvt + bias table)
    prep_kernel<<<(W_TOT + NHEAD * NL * NL + 255) / 256, 256>>>(qkvw, projw, fc1w, fc2w, relb);

    qkv_ln_gemm<<<TOKENS / 128, 256, SMEM_AR3>>>(
        x, n1g, n1b, wc + W_QKV, qkvb, (float*)p_qkv);
    attn_flash<<<dim3(NWIN, NHEAD), 224>>>(mask);
    proj_gemm<<<TOKENS / 128, 256, SMEM_3S>>>(
        (const float*)p_attn, wc + W_PROJ, projb, x, n2g, n2b);
    fc1_gemm<<<TOKENS / 128, 256, SMEM_AR3>>>(
        wc + W_FC1, fc1b, (float*)p_hid);
    fc2_gemm<<<TOKENS / 128, 256, SMEM_3S>>>(
        (const float*)p_hid, wc + W_FC2, fc2b, (const float*)p_x2, out);
}

// round 14
// speedup vs baseline: 1.2056x; 1.0061x over previous
#include <cuda_runtime.h>
#include <math.h>
#include <stdint.h>

// ---------------- problem constants ----------------
#define TOKENS 200704          // 8*8*56*56
#define CD     128
#define NWIN   2048
#define NL     98
#define NHEAD  4

#define SMEM_AR3 (114688)   // A-resident: 64KB A + 3x16KB W stages
#define SMEM_3S  (98304)    // streaming: 3 stages x (16KB A + 16KB W)
#define SMEM_PF1 (114688)   // fused proj+fc1: phase1 96KB stages; phase2 64KB y + 48KB W

// weight cvt offsets (floats)
#define W_QKV  0
#define W_PROJ 49152
#define W_FC1  65536
#define W_FC2  131072
#define W_TOT  196608

// ---------------- scratch ----------------
__device__ float g_qkv [(size_t)TOKENS * 3 * CD];
__device__ float g_bias[(size_t)NHEAD * NL * NL];
__device__ float g_attn[(size_t)TOKENS * CD];
__device__ float g_x2  [(size_t)TOKENS * CD];   // window-token layout
__device__ float g_hid [(size_t)TOKENS * 4 * CD]; // window-token layout
__device__ float g_wcvt[W_TOT];

// ---------------- helpers ----------------
__device__ __forceinline__ float tf32r(float v) {
    uint32_t o;
    asm("cvt.rna.tf32.f32 %0, %1;" : "=r"(o) : "f"(v));
    return __uint_as_float(o);
}
__device__ __forceinline__ void mma_tf32(float c[4],
                                         uint32_t a0, uint32_t a1, uint32_t a2, uint32_t a3,
                                         uint32_t b0, uint32_t b1) {
    asm volatile(
        "mma.sync.aligned.m16n8k8.row.col.f32.tf32.tf32.f32 "
        "{%0,%1,%2,%3}, {%4,%5,%6,%7}, {%8,%9}, {%0,%1,%2,%3};\n"
        : "+f"(c[0]), "+f"(c[1]), "+f"(c[2]), "+f"(c[3])
        : "r"(a0), "r"(a1), "r"(a2), "r"(a3), "r"(b0), "r"(b1));
}
__device__ __forceinline__ uint32_t smem_u32(const void* p) {
    uint32_t a;
    asm("{ .reg .u64 t; cvta.to.shared.u64 t, %1; cvt.u32.u64 %0, t; }" : "=r"(a) : "l"(p));
    return a;
}
#define CP16(dst, src) \
    asm volatile("cp.async.cg.shared.global [%0], [%1], 16;\n" :: "r"(dst), "l"(src))
#define CP_COMMIT() asm volatile("cp.async.commit_group;\n" ::: "memory")
#define CP_WAIT(n)  asm volatile("cp.async.wait_group %0;\n" :: "n"(n) : "memory")

// one 128x128x32 mma sub-block
__device__ __forceinline__ void mma_chunk(const float* __restrict__ Ab,
                                          const float* __restrict__ Bb,
                                          float (*acc)[4][4],
                                          int wm, int wn, int g, int cc) {
    #pragma unroll
    for (int ks = 0; ks < 4; ks++) {
        int k0 = ks * 8;
        int sw = g * 4;
        uint32_t af[4][4];
        #pragma unroll
        for (int mt = 0; mt < 4; mt++) {
            int rb = wm * 64 + mt * 16 + g;
            af[mt][0] = __float_as_uint(Ab[rb * 32       + ((k0 + cc)     ^ sw)]);
            af[mt][1] = __float_as_uint(Ab[(rb + 8) * 32 + ((k0 + cc)     ^ sw)]);
            af[mt][2] = __float_as_uint(Ab[rb * 32       + ((k0 + cc + 4) ^ sw)]);
            af[mt][3] = __float_as_uint(Ab[(rb + 8) * 32 + ((k0 + cc + 4) ^ sw)]);
        }
        uint32_t bf[4][2];
        #pragma unroll
        for (int nt = 0; nt < 4; nt++) {
            int nb = wn * 32 + nt * 8 + g;
            bf[nt][0] = __float_as_uint(Bb[nb * 32 + ((k0 + cc)     ^ sw)]);
            bf[nt][1] = __float_as_uint(Bb[nb * 32 + ((k0 + cc + 4) ^ sw)]);
        }
        #pragma unroll
        for (int mt = 0; mt < 4; mt++)
            #pragma unroll
            for (int nt = 0; nt < 4; nt++)
                mma_tf32(acc[mt][nt], af[mt][0], af[mt][1], af[mt][2], af[mt][3],
                         bf[nt][0], bf[nt][1]);
    }
}

// window row -> spatial token
__device__ __forceinline__ int win_to_spatial(int gr) {
    int win = gr / NL, n = gr % NL;
    int bb = win >> 8, wl = win & 255;
    int dz = wl >> 6, hy = (wl >> 3) & 7, wx = wl & 7;
    int id = n / 49, ih = (n / 7) % 7, iw = n % 7;
    int d  = (dz * 2 + id + 1) & 7;
    int hh = hy * 7 + ih + 3; if (hh >= 56) hh -= 56;
    int ww = wx * 7 + iw + 3; if (ww >= 56) ww -= 56;
    return ((bb * 8 + d) * 56 + hh) * 56 + ww;
}

// ---------------- merged prep: weight tf32 cvt + rel-pos bias ---------------
__global__ void prep_kernel(const float* __restrict__ qkvw, const float* __restrict__ projw,
                            const float* __restrict__ fc1w, const float* __restrict__ fc2w,
                            const float* __restrict__ rel_bias) {
    int i = blockIdx.x * 256 + threadIdx.x;
    if (i < 49152)       g_wcvt[i] = tf32r(qkvw[i]);
    else if (i < 65536)  g_wcvt[i] = tf32r(projw[i - 49152]);
    else if (i < 131072) g_wcvt[i] = tf32r(fc1w[i - 65536]);
    else if (i < 196608) g_wcvt[i] = tf32r(fc2w[i - 131072]);
    else {
        int t = i - 196608;
        if (t >= NHEAD * NL * NL) return;
        int h = t / (NL * NL);
        int r = t % (NL * NL);
        int n = r / NL, m = r % NL;
        int id = n / 49, ih = (n / 7) % 7, iw = n % 7;
        int jd = m / 49, jh = (m / 7) % 7, jw = m % 7;
        int ridx = (id - jd + 1) * 169 + (ih - jh + 6) * 13 + (iw - jw + 6);
        g_bias[t] = rel_bias[ridx * NHEAD + h];
    }
}

// ============ QKV: fused LN1-gather + A-resident, continuous 12-chunk W pipe
__global__ void __launch_bounds__(256, 2)
qkv_ln_gemm(const float* __restrict__ x,
            const float* __restrict__ n1g, const float* __restrict__ n1b,
            const float* __restrict__ W, const float* __restrict__ bias,
            float* __restrict__ C) {
    extern __shared__ float gsm[];
    uint32_t sb = smem_u32(gsm);
    const uint32_t WOFFB = 65536u;
    int tid = threadIdx.x;
    int wid = tid >> 5, lane = tid & 31;
    int g = lane >> 2, cc = lane & 3;
    int m0 = blockIdx.x * 128;
    int wm = wid & 1, wn = wid >> 1;

    int r_ld = tid >> 3, c4_ld = tid & 7;
    uint32_t soff_base = ((uint32_t)r_ld * 32 + (((uint32_t)c4_ld * 4) ^ ((r_ld & 7) * 4))) * 4;

    auto issueW = [&](int t) {
        int n0 = (t >> 2) * 128, k0 = (t & 3) * 32;
        uint32_t dst = sb + WOFFB + (uint32_t)(t % 3) * 16384u;
        #pragma unroll
        for (int i = 0; i < 4; i++) {
            int r = r_ld + i * 32;
            CP16(dst + soff_base + (uint32_t)i * 4096,
                 W + (size_t)(n0 + r) * 128 + k0 + c4_ld * 4);
        }
        CP_COMMIT();
    };

    issueW(0);
    issueW(1);

    // LN1 gather into A smem (overlaps W prefetch)
    {
        float4 gg = reinterpret_cast<const float4*>(n1g)[lane];
        float4 bv = reinterpret_cast<const float4*>(n1b)[lane];
        int cchunk = lane >> 3;
        int colbase = (lane * 4) & 31;
        for (int r = wid; r < 128; r += 8) {
            int src = win_to_spatial(m0 + r);
            float4 v = reinterpret_cast<const float4*>(x + (size_t)src * CD)[lane];
            float s1 = v.x + v.y + v.z + v.w;
            float s2 = v.x*v.x + v.y*v.y + v.z*v.z + v.w*v.w;
            #pragma unroll
            for (int o = 16; o; o >>= 1) {
                s1 += __shfl_xor_sync(0xffffffffu, s1, o);
                s2 += __shfl_xor_sync(0xffffffffu, s2, o);
            }
            float mean = s1 * (1.0f / 128.0f);
            float var  = s2 * (1.0f / 128.0f) - mean * mean;
            float inv  = rsqrtf(var + 1e-5f);
            float4 o;
            o.x = tf32r((v.x - mean) * inv * gg.x + bv.x);
            o.y = tf32r((v.y - mean) * inv * gg.y + bv.y);
            o.z = tf32r((v.z - mean) * inv * gg.z + bv.z);
            o.w = tf32r((v.w - mean) * inv * gg.w + bv.w);
            int col = colbase ^ ((r & 7) * 4);
            *reinterpret_cast<float4*>(gsm + cchunk * 4096 + r * 32 + col) = o;
        }
    }

    float acc[4][4][4];
    for (int t = 0; t < 12; t++) {
        if (t + 1 < 12) CP_WAIT(1); else CP_WAIT(0);
        __syncthreads();
        if ((t & 3) == 0) {
            #pragma unroll
            for (int i = 0; i < 4; i++)
                #pragma unroll
                for (int j = 0; j < 4; j++)
                    #pragma unroll
                    for (int q = 0; q < 4; q++) acc[i][j][q] = 0.0f;
        }
        mma_chunk(gsm + (t & 3) * 4096, gsm + 16384 + (t % 3) * 4096, acc, wm, wn, g, cc);
        if (t + 2 < 12) issueW(t + 2);
        if ((t & 3) == 3) {
            int n0 = (t >> 2) * 128;
            #pragma unroll
            for (int mt = 0; mt < 4; mt++) {
                int r0 = m0 + wm * 64 + mt * 16 + g;
                #pragma unroll
                for (int nt = 0; nt < 4; nt++) {
                    int cb = n0 + wn * 32 + nt * 8 + cc * 2;
                    float2 bb = *reinterpret_cast<const float2*>(bias + cb);
                    #pragma unroll
                    for (int hrow = 0; hrow < 2; hrow++) {
                        int row = r0 + hrow * 8;
                        float2 o;
                        o.x = acc[mt][nt][hrow * 2 + 0] + bb.x;
                        o.y = acc[mt][nt][hrow * 2 + 1] + bb.y;
                        *reinterpret_cast<float2*>(C + (size_t)row * 384 + cb) = o;
                    }
                }
            }
        }
    }
}

// ============ FUSED: proj GEMM + residual + LN2 + fc1 GEMM (GELU) ===========
// phase1 smem: 3 stages x 32KB at [0, 96KB)  (A 16KB + W 16KB per stage)
// phase2 smem: y tile 64KB at [0, 64KB) + W1 3x16KB at [64KB, 112KB)
__global__ void __launch_bounds__(256, 2)
proj_fc1(const float* __restrict__ A, const float* __restrict__ Wp,
         const float* __restrict__ pb, const float* __restrict__ x,
         const float* __restrict__ n2g, const float* __restrict__ n2b,
         const float* __restrict__ W1, const float* __restrict__ b1,
         float* __restrict__ Chid) {
    extern __shared__ float gsm[];
    __shared__ float rs1[128];
    __shared__ float rs2[128];
    uint32_t sb = smem_u32(gsm);
    int tid = threadIdx.x;
    int wid = tid >> 5, lane = tid & 31;
    int g = lane >> 2, cc = lane & 3;
    int m0 = blockIdx.x * 128;
    int wm = wid & 1, wn = wid >> 1;

    int r_ld = tid >> 3, c4_ld = tid & 7;
    uint32_t soff_base = ((uint32_t)r_ld * 32 + (((uint32_t)c4_ld * 4) ^ ((r_ld & 7) * 4))) * 4;

    // ---- phase 1: proj gemm (K=128, 4 chunks, 3-stage) ----
    auto issueP = [&](int kc) {
        int k0 = kc * 32;
        uint32_t st = sb + (uint32_t)(kc % 3) * 32768u;
        #pragma unroll
        for (int i = 0; i < 4; i++) {
            int r = r_ld + i * 32;
            uint32_t soff = soff_base + (uint32_t)i * 4096;
            CP16(st + soff, A + (size_t)(m0 + r) * 128 + k0 + c4_ld * 4);
            CP16(st + 16384u + soff, Wp + (size_t)r * 128 + k0 + c4_ld * 4);
        }
        CP_COMMIT();
    };

    if (tid < 128) { rs1[tid] = 0.0f; rs2[tid] = 0.0f; }

    float acc[4][4][4];
    #pragma unroll
    for (int i = 0; i < 4; i++)
        #pragma unroll
        for (int j = 0; j < 4; j++)
            #pragma unroll
            for (int t = 0; t < 4; t++) acc[i][j][t] = 0.0f;

    issueP(0);
    issueP(1);
    for (int kc = 0; kc < 4; kc++) {
        if (kc + 1 < 4) CP_WAIT(1); else CP_WAIT(0);
        __syncthreads();
        const float* st = gsm + (kc % 3) * 8192;
        mma_chunk(st, st + 4096, acc, wm, wn, g, cc);
        if (kc + 2 < 4) issueP(kc + 2);
    }
    __syncthreads();   // all mma reads of stage buffers complete

    // ---- prefetch W1 chunks 0,1 (into [64KB,96KB) — stage2 region, now free)
    auto issueW1 = [&](int t) {
        int n0 = (t >> 2) * 128, k0 = (t & 3) * 32;
        uint32_t dst = sb + 65536u + (uint32_t)(t % 3) * 16384u;
        #pragma unroll
        for (int i = 0; i < 4; i++) {
            int r = r_ld + i * 32;
            CP16(dst + soff_base + (uint32_t)i * 4096,
                 W1 + (size_t)(n0 + r) * 128 + k0 + c4_ld * 4);
        }
        CP_COMMIT();
    };
    issueW1(0);
    issueW1(1);

    // ---- epilogue A: v = acc + pb + x[spatial]; row sums; write x2 (window)
    int tsp[4][2];
    #pragma unroll
    for (int mt = 0; mt < 4; mt++) {
        int rl = wm * 64 + mt * 16 + g;
        tsp[mt][0] = win_to_spatial(m0 + rl);
        tsp[mt][1] = win_to_spatial(m0 + rl + 8);
    }
    #pragma unroll
    for (int mt = 0; mt < 4; mt++) {
        #pragma unroll
        for (int hrow = 0; hrow < 2; hrow++) {
            int rl = wm * 64 + mt * 16 + g + hrow * 8;
            float s1 = 0.0f, s2 = 0.0f;
            #pragma unroll
            for (int nt = 0; nt < 4; nt++) {
                int cb = wn * 32 + nt * 8 + cc * 2;
                float2 bb = *reinterpret_cast<const float2*>(pb + cb);
                float2 xv = *reinterpret_cast<const float2*>(x + (size_t)tsp[mt][hrow] * CD + cb);
                float v0 = acc[mt][nt][hrow * 2 + 0] + bb.x + xv.x;
                float v1 = acc[mt][nt][hrow * 2 + 1] + bb.y + xv.y;
                acc[mt][nt][hrow * 2 + 0] = v0;
                acc[mt][nt][hrow * 2 + 1] = v1;
                s1 += v0 + v1;
                s2 += v0 * v0 + v1 * v1;
                float2 x2o; x2o.x = v0; x2o.y = v1;
                *reinterpret_cast<float2*>(g_x2 + (size_t)(m0 + rl) * CD + cb) = x2o;
            }
            atomicAdd(&rs1[rl], s1);
            atomicAdd(&rs2[rl], s2);
        }
    }
    __syncthreads();

    // ---- epilogue B: LN2 -> y into smem [0,64KB) (swizzled tf32 A-layout) ----
    #pragma unroll
    for (int mt = 0; mt < 4; mt++) {
        #pragma unroll
        for (int hrow = 0; hrow < 2; hrow++) {
            int rl = wm * 64 + mt * 16 + g + hrow * 8;
            float mean = rs1[rl] * (1.0f / 128.0f);
            float var  = rs2[rl] * (1.0f / 128.0f) - mean * mean;
            float inv  = rsqrtf(var + 1e-5f);
            #pragma unroll
            for (int nt = 0; nt < 4; nt++) {
                int cl = wn * 32 + nt * 8 + cc * 2;
                float v0 = acc[mt][nt][hrow * 2 + 0];
                float v1 = acc[mt][nt][hrow * 2 + 1];
                float2 gg = *reinterpret_cast<const float2*>(n2g + cl);
                float2 bv = *reinterpret_cast<const float2*>(n2b + cl);
                float2 yo;
                yo.x = tf32r((v0 - mean) * inv * gg.x + bv.x);
                yo.y = tf32r((v1 - mean) * inv * gg.y + bv.y);
                int c32 = cl & 31;
                int scol = c32 ^ ((rl & 7) * 4);
                *reinterpret_cast<float2*>(gsm + wn * 4096 + rl * 32 + scol) = yo;
            }
        }
    }

    // ---- phase 2: fc1 (y-resident, 16 W1 chunks, GELU -> Chid) ----
    for (int t = 0; t < 16; t++) {
        if (t + 1 < 16) CP_WAIT(1); else CP_WAIT(0);
        __syncthreads();      // also orders y smem stores before first mma
        if ((t & 3) == 0) {
            #pragma unroll
            for (int i = 0; i < 4; i++)
                #pragma unroll
                for (int j = 0; j < 4; j++)
                    #pragma unroll
                    for (int q = 0; q < 4; q++) acc[i][j][q] = 0.0f;
        }
        mma_chunk(gsm + (t & 3) * 4096, gsm + 16384 + (t % 3) * 4096, acc, wm, wn, g, cc);
        if (t + 2 < 16) issueW1(t + 2);
        if ((t & 3) == 3) {
            int n0 = (t >> 2) * 128;
            #pragma unroll
            for (int mt = 0; mt < 4; mt++) {
                int r0 = m0 + wm * 64 + mt * 16 + g;
                #pragma unroll
                for (int nt = 0; nt < 4; nt++) {
                    int cb = n0 + wn * 32 + nt * 8 + cc * 2;
                    float2 bb = *reinterpret_cast<const float2*>(b1 + cb);
                    #pragma unroll
                    for (int hrow = 0; hrow < 2; hrow++) {
                        int row = r0 + hrow * 8;
                        float v0 = acc[mt][nt][hrow * 2 + 0] + bb.x;
                        float v1 = acc[mt][nt][hrow * 2 + 1] + bb.y;
                        v0 = tf32r(0.5f * v0 * (1.0f + erff(v0 * 0.70710678118654752f)));
                        v1 = tf32r(0.5f * v1 * (1.0f + erff(v1 * 0.70710678118654752f)));
                        float2 o; o.x = v0; o.y = v1;
                        *reinterpret_cast<float2*>(Chid + (size_t)row * 512 + cb) = o;
                    }
                }
            }
        }
    }
}

// ============ fc2: streaming 3-stage, +bias +residual(window) -> out(scatter)
__global__ void __launch_bounds__(256, 2)
fc2_gemm(const float* __restrict__ A, const float* __restrict__ W,
         const float* __restrict__ bias, const float* __restrict__ res,
         float* __restrict__ C) {
    extern __shared__ float gsm[];
    uint32_t sb = smem_u32(gsm);
    int tid = threadIdx.x;
    int wid = tid >> 5, lane = tid & 31;
    int g = lane >> 2, cc = lane & 3;
    int m0 = blockIdx.x * 128;
    int wm = wid & 1, wn = wid >> 1;

    float acc[4][4][4];
    #pragma unroll
    for (int i = 0; i < 4; i++)
        #pragma unroll
        for (int j = 0; j < 4; j++)
            #pragma unroll
            for (int t = 0; t < 4; t++) acc[i][j][t] = 0.0f;

    int r_ld = tid >> 3, c4_ld = tid & 7;
    uint32_t soff_base = ((uint32_t)r_ld * 32 + (((uint32_t)c4_ld * 4) ^ ((r_ld & 7) * 4))) * 4;

    auto issue = [&](int kc) {
        int k0 = kc * 32;
        uint32_t st = sb + (uint32_t)(kc % 3) * 32768u;
        #pragma unroll
        for (int i = 0; i < 4; i++) {
            int r = r_ld + i * 32;
            uint32_t soff = soff_base + (uint32_t)i * 4096;
            CP16(st + soff, A + (size_t)(m0 + r) * 512 + k0 + c4_ld * 4);
            CP16(st + 16384u + soff, W + (size_t)r * 512 + k0 + c4_ld * 4);
        }
        CP_COMMIT();
    };

    issue(0);
    issue(1);
    for (int kc = 0; kc < 16; kc++) {
        if (kc + 1 < 16) CP_WAIT(1); else CP_WAIT(0);
        __syncthreads();
        const float* st = gsm + (kc % 3) * 8192;
        mma_chunk(st, st + 4096, acc, wm, wn, g, cc);
        if (kc + 2 < 16) issue(kc + 2);
    }

    #pragma unroll
    for (int mt = 0; mt < 4; mt++) {
        #pragma unroll
        for (int hrow = 0; hrow < 2; hrow++) {
            int rl = wm * 64 + mt * 16 + g + hrow * 8;
            int rsp = win_to_spatial(m0 + rl);
            #pragma unroll
            for (int nt = 0; nt < 4; nt++) {
                int cb = wn * 32 + nt * 8 + cc * 2;
                float2 bb = *reinterpret_cast<const float2*>(bias + cb);
                float2 r2 = *reinterpret_cast<const float2*>(res + (size_t)(m0 + rl) * CD + cb);
                float2 o;
                o.x = acc[mt][nt][hrow * 2 + 0] + bb.x + r2.x;
                o.y = acc[mt][nt][hrow * 2 + 1] + bb.y + r2.y;
                *reinterpret_cast<float2*>(C + (size_t)rsp * CD + cb) = o;
            }
        }
    }
}

// ---------------- flash-style register attention ----------------
__global__ void __launch_bounds__(224, 3)
attn_flash(const float* __restrict__ mask) {
    __shared__ float Qs[112 * 32];
    __shared__ float Ks[104 * 32];
    __shared__ float Vs[104 * 32];
    int win = blockIdx.x, h = blockIdx.y;
    int tid = threadIdx.x, wid = tid >> 5, lane = tid & 31;
    int g = lane >> 2, cc = lane & 3;

    for (int i = tid; i < 14 * 32; i += 224) Qs[98 * 32 + i] = 0.0f;
    if (tid < 192) { Ks[98 * 32 + tid] = 0.0f; Vs[98 * 32 + tid] = 0.0f; }
    const float* base = g_qkv + (size_t)win * NL * 384 + h * 32;
    for (int e = tid; e < 98 * 24; e += 224) {
        int tok = e / 24, p = e - tok * 24;
        int which = p >> 3, c4 = p & 7;
        float4 v = *reinterpret_cast<const float4*>(base + (size_t)tok * 384 + which * 128 + c4 * 4);
        if (which == 0) {
            const float sc = 0.17677669529663689f;
            v.x *= sc; v.y *= sc; v.z *= sc; v.w *= sc;
        }
        float4 t;
        t.x = tf32r(v.x); t.y = tf32r(v.y); t.z = tf32r(v.z); t.w = tf32r(v.w);
        int col = (c4 * 4) ^ ((tok & 7) * 4);
        float* dst = (which == 0 ? Qs : which == 1 ? Ks : Vs) + tok * 32 + col;
        *reinterpret_cast<float4*>(dst) = t;
    }
    __syncthreads();

    int m0 = wid * 16;
    int r0 = m0 + g, r1 = m0 + g + 8;
    int sw = g * 4;

    uint32_t aq[4][4];
    #pragma unroll
    for (int kc = 0; kc < 4; kc++) {
        int col0 = (kc * 8 + cc) ^ sw;
        int col1 = (kc * 8 + cc + 4) ^ sw;
        aq[kc][0] = __float_as_uint(Qs[r0 * 32 + col0]);
        aq[kc][1] = __float_as_uint(Qs[r1 * 32 + col0]);
        aq[kc][2] = __float_as_uint(Qs[r0 * 32 + col1]);
        aq[kc][3] = __float_as_uint(Qs[r1 * 32 + col1]);
    }

    float sacc[13][4];
    #pragma unroll
    for (int nt = 0; nt < 13; nt++) {
        float s[4] = {0.f, 0.f, 0.f, 0.f};
        int nr = nt * 8 + g;
        #pragma unroll
        for (int kc = 0; kc < 4; kc++) {
            int col0 = (kc * 8 + cc) ^ sw;
            int col1 = (kc * 8 + cc + 4) ^ sw;
            uint32_t b0 = __float_as_uint(Ks[nr * 32 + col0]);
            uint32_t b1 = __float_as_uint(Ks[nr * 32 + col1]);
            mma_tf32(s, aq[kc][0], aq[kc][1], aq[kc][2], aq[kc][3], b0, b1);
        }
        sacc[nt][0] = s[0]; sacc[nt][1] = s[1]; sacc[nt][2] = s[2]; sacc[nt][3] = s[3];
    }

    {
        const float* bm = g_bias + (size_t)h * (NL * NL);
        const float* mk = mask + (size_t)(win & 255) * (NL * NL);
        int rc0 = (r0 < 98 ? r0 : 97) * 98;
        int rc1 = (r1 < 98 ? r1 : 97) * 98;
        #pragma unroll
        for (int nt = 0; nt < 13; nt++) {
            int col = nt * 8 + 2 * cc;
            if (col < 98) {
                sacc[nt][0] += __ldg(bm + rc0 + col) + __ldg(mk + rc0 + col);
                sacc[nt][2] += __ldg(bm + rc1 + col) + __ldg(mk + rc1 + col);
            } else { sacc[nt][0] = -1.0e38f; sacc[nt][2] = -1.0e38f; }
            if (col + 1 < 98) {
                sacc[nt][1] += __ldg(bm + rc0 + col + 1) + __ldg(mk + rc0 + col + 1);
                sacc[nt][3] += __ldg(bm + rc1 + col + 1) + __ldg(mk + rc1 + col + 1);
            } else { sacc[nt][1] = -1.0e38f; sacc[nt][3] = -1.0e38f; }
        }
    }

    float mx0 = -1.0e38f, mx1 = -1.0e38f;
    #pragma unroll
    for (int nt = 0; nt < 13; nt++) {
        mx0 = fmaxf(mx0, fmaxf(sacc[nt][0], sacc[nt][1]));
        mx1 = fmaxf(mx1, fmaxf(sacc[nt][2], sacc[nt][3]));
    }
    mx0 = fmaxf(mx0, __shfl_xor_sync(0xffffffffu, mx0, 1));
    mx0 = fmaxf(mx0, __shfl_xor_sync(0xffffffffu, mx0, 2));
    mx1 = fmaxf(mx1, __shfl_xor_sync(0xffffffffu, mx1, 1));
    mx1 = fmaxf(mx1, __shfl_xor_sync(0xffffffffu, mx1, 2));
    float sm0 = 0.f, sm1 = 0.f;
    #pragma unroll
    for (int nt = 0; nt < 13; nt++) {
        sacc[nt][0] = __expf(sacc[nt][0] - mx0);
        sacc[nt][1] = __expf(sacc[nt][1] - mx0);
        sacc[nt][2] = __expf(sacc[nt][2] - mx1);
        sacc[nt][3] = __expf(sacc[nt][3] - mx1);
        sm0 += sacc[nt][0] + sacc[nt][1];
        sm1 += sacc[nt][2] + sacc[nt][3];
    }
    sm0 += __shfl_xor_sync(0xffffffffu, sm0, 1);
    sm0 += __shfl_xor_sync(0xffffffffu, sm0, 2);
    sm1 += __shfl_xor_sync(0xffffffffu, sm1, 1);
    sm1 += __shfl_xor_sync(0xffffffffu, sm1, 2);
    float iv0 = 1.0f / sm0, iv1 = 1.0f / sm1;
    #pragma unroll
    for (int nt = 0; nt < 13; nt++) {
        sacc[nt][0] = tf32r(sacc[nt][0] * iv0);
        sacc[nt][1] = tf32r(sacc[nt][1] * iv0);
        sacc[nt][2] = tf32r(sacc[nt][2] * iv1);
        sacc[nt][3] = tf32r(sacc[nt][3] * iv1);
    }

    float oacc[4][4];
    #pragma unroll
    for (int vt = 0; vt < 4; vt++)
        #pragma unroll
        for (int t = 0; t < 4; t++) oacc[vt][t] = 0.0f;
    int qb = lane & ~3;
    int src0 = qb + (cc >> 1);
    bool odd = (cc & 1);
    #pragma unroll
    for (int kc = 0; kc < 13; kc++) {
        float p0 = sacc[kc][0], p1 = sacc[kc][1], p2 = sacc[kc][2], p3 = sacc[kc][3];
        float t0 = __shfl_sync(0xffffffffu, p0, src0);
        float t1 = __shfl_sync(0xffffffffu, p1, src0);
        float u0 = __shfl_sync(0xffffffffu, p0, src0 + 2);
        float u1 = __shfl_sync(0xffffffffu, p1, src0 + 2);
        float t2 = __shfl_sync(0xffffffffu, p2, src0);
        float t3 = __shfl_sync(0xffffffffu, p3, src0);
        float u2 = __shfl_sync(0xffffffffu, p2, src0 + 2);
        float u3 = __shfl_sync(0xffffffffu, p3, src0 + 2);
        uint32_t a0 = __float_as_uint(odd ? t1 : t0);
        uint32_t a2 = __float_as_uint(odd ? u1 : u0);
        uint32_t a1 = __float_as_uint(odd ? t3 : t2);
        uint32_t a3 = __float_as_uint(odd ? u3 : u2);
        int k0 = kc * 8;
        #pragma unroll
        for (int vt = 0; vt < 4; vt++) {
            uint32_t b0 = __float_as_uint(Vs[(k0 + cc) * 32     + ((vt * 8 + g) ^ (cc * 4))]);
            uint32_t b1 = __float_as_uint(Vs[(k0 + cc + 4) * 32 + ((vt * 8 + g) ^ (cc * 4 + 16))]);
            mma_tf32(oacc[vt], a0, a1, a2, a3, b0, b1);
        }
    }

    float* ob = g_attn + (size_t)win * NL * CD + h * 32;
    #pragma unroll
    for (int vt = 0; vt < 4; vt++) {
        int cb = vt * 8 + 2 * cc;
        if (r0 < NL) {
            float2 o; o.x = tf32r(oacc[vt][0]); o.y = tf32r(oacc[vt][1]);
            *reinterpret_cast<float2*>(ob + (size_t)r0 * CD + cb) = o;
        }
        if (r1 < NL) {
            float2 o; o.x = tf32r(oacc[vt][2]); o.y = tf32r(oacc[vt][3]);
            *reinterpret_cast<float2*>(ob + (size_t)r1 * CD + cb) = o;
        }
    }
}

// ---------------- launch ----------------
extern "C" void kernel_launch(void* const* d_in, const int* in_sizes, int n_in,
                              void* d_out, int out_size) {
    const float* x     = (const float*)d_in[0];
    const float* mask  = (const float*)d_in[1];
    const float* n1g   = (const float*)d_in[2];
    const float* n1b   = (const float*)d_in[3];
    const float* qkvw  = (const float*)d_in[4];
    const float* qkvb  = (const float*)d_in[5];
    const float* relb  = (const float*)d_in[6];
    const float* projw = (const float*)d_in[7];
    const float* projb = (const float*)d_in[8];
    const float* n2g   = (const float*)d_in[9];
    const float* n2b   = (const float*)d_in[10];
    const float* fc1w  = (const float*)d_in[11];
    const float* fc1b  = (const float*)d_in[12];
    const float* fc2w  = (const float*)d_in[13];
    const float* fc2b  = (const float*)d_in[14];
    float* out = (float*)d_out;

    void *p_qkv, *p_attn, *p_x2, *p_hid, *p_w;
    cudaGetSymbolAddress(&p_qkv,  g_qkv);
    cudaGetSymbolAddress(&p_attn, g_attn);
    cudaGetSymbolAddress(&p_x2,   g_x2);
    cudaGetSymbolAddress(&p_hid,  g_hid);
    cudaGetSymbolAddress(&p_w,    g_wcvt);
    float* wc = (float*)p_w;

    cudaFuncSetAttribute(qkv_ln_gemm, cudaFuncAttributeMaxDynamicSharedMemorySize, SMEM_AR3);
    cudaFuncSetAttribute(proj_fc1,    cudaFuncAttributeMaxDynamicSharedMemorySize, SMEM_PF1);
    cudaFuncSetAttribute(fc2_gemm,    cudaFuncAttributeMaxDynamicSharedMemorySize, SMEM_3S);

    prep_kernel<<<(W_TOT + NHEAD * NL * NL + 255) / 256, 256>>>(qkvw, projw, fc1w, fc2w, relb);

    qkv_ln_gemm<<<TOKENS / 128, 256, SMEM_AR3>>>(
        x, n1g, n1b, wc + W_QKV, qkvb, (float*)p_qkv);
    attn_flash<<<dim3(NWIN, NHEAD), 224>>>(mask);
    proj_fc1<<<TOKENS / 128, 256, SMEM_PF1>>>(
        (const float*)p_attn, wc + W_PROJ, projb, x, n2g, n2b,
        wc + W_FC1, fc1b, (float*)p_hid);
    fc2_gemm<<<TOKENS / 128, 256, SMEM_3S>>>(
        (const float*)p_hid, wc + W_FC2, fc2b, (const float*)p_x2, out);
}

// round 17
// speedup vs baseline: 1.2865x; 1.0671x over previous
#include <cuda_runtime.h>
#include <math.h>
#include <stdint.h>

// ---------------- problem constants ----------------
#define TOKENS 200704          // 8*8*56*56
#define CD     128
#define NWIN   2048
#define NL     98
#define NHEAD  4

#define SMEM_AR3 (114688)   // A-resident: 64KB A + 3x16KB W stages
#define SMEM_3S  (98304)    // streaming: 3 stages x (16KB A + 16KB W)
#define SMEM_PF1 (114688)   // fused proj+fc1

// weight cvt offsets (floats)
#define W_QKV  0
#define W_PROJ 49152
#define W_FC1  65536
#define W_FC2  131072
#define W_TOT  196608

// ---------------- scratch ----------------
__device__ float g_qkv [(size_t)TOKENS * 3 * CD];
__device__ float g_bias[(size_t)NHEAD * NL * NL];
__device__ float g_attn[(size_t)TOKENS * CD];
__device__ float g_x2  [(size_t)TOKENS * CD];     // window-token layout
__device__ float g_hid [(size_t)TOKENS * 4 * CD]; // window-token layout
__device__ float g_wcvt[W_TOT];

// ---------------- helpers ----------------
__device__ __forceinline__ float tf32r(float v) {
    uint32_t o;
    asm("cvt.rna.tf32.f32 %0, %1;" : "=r"(o) : "f"(v));
    return __uint_as_float(o);
}
__device__ __forceinline__ void mma_tf32(float c[4],
                                         uint32_t a0, uint32_t a1, uint32_t a2, uint32_t a3,
                                         uint32_t b0, uint32_t b1) {
    asm volatile(
        "mma.sync.aligned.m16n8k8.row.col.f32.tf32.tf32.f32 "
        "{%0,%1,%2,%3}, {%4,%5,%6,%7}, {%8,%9}, {%0,%1,%2,%3};\n"
        : "+f"(c[0]), "+f"(c[1]), "+f"(c[2]), "+f"(c[3])
        : "r"(a0), "r"(a1), "r"(a2), "r"(a3), "r"(b0), "r"(b1));
}
__device__ __forceinline__ uint32_t smem_u32(const void* p) {
    uint32_t a;
    asm("{ .reg .u64 t; cvta.to.shared.u64 t, %1; cvt.u32.u64 %0, t; }" : "=r"(a) : "l"(p));
    return a;
}
#define CP16(dst, src) \
    asm volatile("cp.async.cg.shared.global [%0], [%1], 16;\n" :: "r"(dst), "l"(src))
#define CP_COMMIT() asm volatile("cp.async.commit_group;\n" ::: "memory")
#define CP_WAIT(n)  asm volatile("cp.async.wait_group %0;\n" :: "n"(n) : "memory")

// one 128x128x32 mma sub-block
__device__ __forceinline__ void mma_chunk(const float* __restrict__ Ab,
                                          const float* __restrict__ Bb,
                                          float (*acc)[4][4],
                                          int wm, int wn, int g, int cc) {
    #pragma unroll
    for (int ks = 0; ks < 4; ks++) {
        int k0 = ks * 8;
        int sw = g * 4;
        uint32_t af[4][4];
        #pragma unroll
        for (int mt = 0; mt < 4; mt++) {
            int rb = wm * 64 + mt * 16 + g;
            af[mt][0] = __float_as_uint(Ab[rb * 32       + ((k0 + cc)     ^ sw)]);
            af[mt][1] = __float_as_uint(Ab[(rb + 8) * 32 + ((k0 + cc)     ^ sw)]);
            af[mt][2] = __float_as_uint(Ab[rb * 32       + ((k0 + cc + 4) ^ sw)]);
            af[mt][3] = __float_as_uint(Ab[(rb + 8) * 32 + ((k0 + cc + 4) ^ sw)]);
        }
        uint32_t bf[4][2];
        #pragma unroll
        for (int nt = 0; nt < 4; nt++) {
            int nb = wn * 32 + nt * 8 + g;
            bf[nt][0] = __float_as_uint(Bb[nb * 32 + ((k0 + cc)     ^ sw)]);
            bf[nt][1] = __float_as_uint(Bb[nb * 32 + ((k0 + cc + 4) ^ sw)]);
        }
        #pragma unroll
        for (int mt = 0; mt < 4; mt++)
            #pragma unroll
            for (int nt = 0; nt < 4; nt++)
                mma_tf32(acc[mt][nt], af[mt][0], af[mt][1], af[mt][2], af[mt][3],
                         bf[nt][0], bf[nt][1]);
    }
}

// window row -> spatial token
__device__ __forceinline__ int win_to_spatial(int gr) {
    int win = gr / NL, n = gr % NL;
    int bb = win >> 8, wl = win & 255;
    int dz = wl >> 6, hy = (wl >> 3) & 7, wx = wl & 7;
    int id = n / 49, ih = (n / 7) % 7, iw = n % 7;
    int d  = (dz * 2 + id + 1) & 7;
    int hh = hy * 7 + ih + 3; if (hh >= 56) hh -= 56;
    int ww = wx * 7 + iw + 3; if (ww >= 56) ww -= 56;
    return ((bb * 8 + d) * 56 + hh) * 56 + ww;
}

// ---------------- merged prep: weight tf32 cvt + rel-pos bias ---------------
__global__ void prep_kernel(const float* __restrict__ qkvw, const float* __restrict__ projw,
                            const float* __restrict__ fc1w, const float* __restrict__ fc2w,
                            const float* __restrict__ rel_bias) {
    int i = blockIdx.x * 256 + threadIdx.x;
    if (i < 49152)       g_wcvt[i] = tf32r(qkvw[i]);
    else if (i < 65536)  g_wcvt[i] = tf32r(projw[i - 49152]);
    else if (i < 131072) g_wcvt[i] = tf32r(fc1w[i - 65536]);
    else if (i < 196608) g_wcvt[i] = tf32r(fc2w[i - 131072]);
    else {
        int t = i - 196608;
        if (t >= NHEAD * NL * NL) return;
        int h = t / (NL * NL);
        int r = t % (NL * NL);
        int n = r / NL, m = r % NL;
        int id = n / 49, ih = (n / 7) % 7, iw = n % 7;
        int jd = m / 49, jh = (m / 7) % 7, jw = m % 7;
        int ridx = (id - jd + 1) * 169 + (ih - jh + 6) * 13 + (iw - jw + 6);
        g_bias[t] = rel_bias[ridx * NHEAD + h];
    }
}

// ============ QKV: fused LN1-gather + A-resident, continuous 12-chunk W pipe
__global__ void __launch_bounds__(256, 2)
qkv_ln_gemm(const float* __restrict__ x,
            const float* __restrict__ n1g, const float* __restrict__ n1b,
            const float* __restrict__ W, const float* __restrict__ bias,
            float* __restrict__ C) {
    extern __shared__ float gsm[];
    uint32_t sb = smem_u32(gsm);
    const uint32_t WOFFB = 65536u;
    int tid = threadIdx.x;
    int wid = tid >> 5, lane = tid & 31;
    int g = lane >> 2, cc = lane & 3;
    int m0 = blockIdx.x * 128;
    int wm = wid & 1, wn = wid >> 1;

    int r_ld = tid >> 3, c4_ld = tid & 7;
    uint32_t soff_base = ((uint32_t)r_ld * 32 + (((uint32_t)c4_ld * 4) ^ ((r_ld & 7) * 4))) * 4;

    auto issueW = [&](int t) {
        int n0 = (t >> 2) * 128, k0 = (t & 3) * 32;
        uint32_t dst = sb + WOFFB + (uint32_t)(t % 3) * 16384u;
        #pragma unroll
        for (int i = 0; i < 4; i++) {
            int r = r_ld + i * 32;
            CP16(dst + soff_base + (uint32_t)i * 4096,
                 W + (size_t)(n0 + r) * 128 + k0 + c4_ld * 4);
        }
        CP_COMMIT();
    };

    issueW(0);
    issueW(1);

    // LN1 gather into A smem (overlaps W prefetch)
    {
        float4 gg = reinterpret_cast<const float4*>(n1g)[lane];
        float4 bv = reinterpret_cast<const float4*>(n1b)[lane];
        int cchunk = lane >> 3;
        int colbase = (lane * 4) & 31;
        for (int r = wid; r < 128; r += 8) {
            int src = win_to_spatial(m0 + r);
            float4 v = reinterpret_cast<const float4*>(x + (size_t)src * CD)[lane];
            float s1 = v.x + v.y + v.z + v.w;
            float s2 = v.x*v.x + v.y*v.y + v.z*v.z + v.w*v.w;
            #pragma unroll
            for (int o = 16; o; o >>= 1) {
                s1 += __shfl_xor_sync(0xffffffffu, s1, o);
                s2 += __shfl_xor_sync(0xffffffffu, s2, o);
            }
            float mean = s1 * (1.0f / 128.0f);
            float var  = s2 * (1.0f / 128.0f) - mean * mean;
            float inv  = rsqrtf(var + 1e-5f);
            float4 o;
            o.x = tf32r((v.x - mean) * inv * gg.x + bv.x);
            o.y = tf32r((v.y - mean) * inv * gg.y + bv.y);
            o.z = tf32r((v.z - mean) * inv * gg.z + bv.z);
            o.w = tf32r((v.w - mean) * inv * gg.w + bv.w);
            int col = colbase ^ ((r & 7) * 4);
            *reinterpret_cast<float4*>(gsm + cchunk * 4096 + r * 32 + col) = o;
        }
    }

    float acc[4][4][4];
    for (int t = 0; t < 12; t++) {
        if (t + 1 < 12) CP_WAIT(1); else CP_WAIT(0);
        __syncthreads();
        if ((t & 3) == 0) {
            #pragma unroll
            for (int i = 0; i < 4; i++)
                #pragma unroll
                for (int j = 0; j < 4; j++)
                    #pragma unroll
                    for (int q = 0; q < 4; q++) acc[i][j][q] = 0.0f;
        }
        mma_chunk(gsm + (t & 3) * 4096, gsm + 16384 + (t % 3) * 4096, acc, wm, wn, g, cc);
        if (t + 2 < 12) issueW(t + 2);
        if ((t & 3) == 3) {
            int n0 = (t >> 2) * 128;
            #pragma unroll
            for (int mt = 0; mt < 4; mt++) {
                int r0 = m0 + wm * 64 + mt * 16 + g;
                #pragma unroll
                for (int nt = 0; nt < 4; nt++) {
                    int cb = n0 + wn * 32 + nt * 8 + cc * 2;
                    float2 bb = *reinterpret_cast<const float2*>(bias + cb);
                    #pragma unroll
                    for (int hrow = 0; hrow < 2; hrow++) {
                        int row = r0 + hrow * 8;
                        float2 o;
                        o.x = acc[mt][nt][hrow * 2 + 0] + bb.x;
                        o.y = acc[mt][nt][hrow * 2 + 1] + bb.y;
                        *reinterpret_cast<float2*>(C + (size_t)row * 384 + cb) = o;
                    }
                }
            }
        }
    }
}

// ============ FUSED: proj GEMM + residual + LN2 + fc1 GEMM (GELU) ===========
__global__ void __launch_bounds__(256, 2)
proj_fc1(const float* __restrict__ A, const float* __restrict__ Wp,
         const float* __restrict__ pb, const float* __restrict__ x,
         const float* __restrict__ n2g, const float* __restrict__ n2b,
         const float* __restrict__ W1, const float* __restrict__ b1,
         float* __restrict__ Chid) {
    extern __shared__ float gsm[];
    __shared__ float rs1[128];
    __shared__ float rs2[128];
    uint32_t sb = smem_u32(gsm);
    int tid = threadIdx.x;
    int wid = tid >> 5, lane = tid & 31;
    int g = lane >> 2, cc = lane & 3;
    int m0 = blockIdx.x * 128;
    int wm = wid & 1, wn = wid >> 1;

    int r_ld = tid >> 3, c4_ld = tid & 7;
    uint32_t soff_base = ((uint32_t)r_ld * 32 + (((uint32_t)c4_ld * 4) ^ ((r_ld & 7) * 4))) * 4;

    auto issueP = [&](int kc) {
        int k0 = kc * 32;
        uint32_t st = sb + (uint32_t)(kc % 3) * 32768u;
        #pragma unroll
        for (int i = 0; i < 4; i++) {
            int r = r_ld + i * 32;
            uint32_t soff = soff_base + (uint32_t)i * 4096;
            CP16(st + soff, A + (size_t)(m0 + r) * 128 + k0 + c4_ld * 4);
            CP16(st + 16384u + soff, Wp + (size_t)r * 128 + k0 + c4_ld * 4);
        }
        CP_COMMIT();
    };

    if (tid < 128) { rs1[tid] = 0.0f; rs2[tid] = 0.0f; }

    float acc[4][4][4];
    #pragma unroll
    for (int i = 0; i < 4; i++)
        #pragma unroll
        for (int j = 0; j < 4; j++)
            #pragma unroll
            for (int t = 0; t < 4; t++) acc[i][j][t] = 0.0f;

    issueP(0);
    issueP(1);
    for (int kc = 0; kc < 4; kc++) {
        if (kc + 1 < 4) CP_WAIT(1); else CP_WAIT(0);
        __syncthreads();
        const float* st = gsm + (kc % 3) * 8192;
        mma_chunk(st, st + 4096, acc, wm, wn, g, cc);
        if (kc + 2 < 4) issueP(kc + 2);
    }
    __syncthreads();

    auto issueW1 = [&](int t) {
        int n0 = (t >> 2) * 128, k0 = (t & 3) * 32;
        uint32_t dst = sb + 65536u + (uint32_t)(t % 3) * 16384u;
        #pragma unroll
        for (int i = 0; i < 4; i++) {
            int r = r_ld + i * 32;
            CP16(dst + soff_base + (uint32_t)i * 4096,
                 W1 + (size_t)(n0 + r) * 128 + k0 + c4_ld * 4);
        }
        CP_COMMIT();
    };
    issueW1(0);
    issueW1(1);

    int tsp[4][2];
    #pragma unroll
    for (int mt = 0; mt < 4; mt++) {
        int rl = wm * 64 + mt * 16 + g;
        tsp[mt][0] = win_to_spatial(m0 + rl);
        tsp[mt][1] = win_to_spatial(m0 + rl + 8);
    }
    #pragma unroll
    for (int mt = 0; mt < 4; mt++) {
        #pragma unroll
        for (int hrow = 0; hrow < 2; hrow++) {
            int rl = wm * 64 + mt * 16 + g + hrow * 8;
            float s1 = 0.0f, s2 = 0.0f;
            #pragma unroll
            for (int nt = 0; nt < 4; nt++) {
                int cb = wn * 32 + nt * 8 + cc * 2;
                float2 bb = *reinterpret_cast<const float2*>(pb + cb);
                float2 xv = *reinterpret_cast<const float2*>(x + (size_t)tsp[mt][hrow] * CD + cb);
                float v0 = acc[mt][nt][hrow * 2 + 0] + bb.x + xv.x;
                float v1 = acc[mt][nt][hrow * 2 + 1] + bb.y + xv.y;
                acc[mt][nt][hrow * 2 + 0] = v0;
                acc[mt][nt][hrow * 2 + 1] = v1;
                s1 += v0 + v1;
                s2 += v0 * v0 + v1 * v1;
                float2 x2o; x2o.x = v0; x2o.y = v1;
                *reinterpret_cast<float2*>(g_x2 + (size_t)(m0 + rl) * CD + cb) = x2o;
            }
            atomicAdd(&rs1[rl], s1);
            atomicAdd(&rs2[rl], s2);
        }
    }
    __syncthreads();

    #pragma unroll
    for (int mt = 0; mt < 4; mt++) {
        #pragma unroll
        for (int hrow = 0; hrow < 2; hrow++) {
            int rl = wm * 64 + mt * 16 + g + hrow * 8;
            float mean = rs1[rl] * (1.0f / 128.0f);
            float var  = rs2[rl] * (1.0f / 128.0f) - mean * mean;
            float inv  = rsqrtf(var + 1e-5f);
            #pragma unroll
            for (int nt = 0; nt < 4; nt++) {
                int cl = wn * 32 + nt * 8 + cc * 2;
                float v0 = acc[mt][nt][hrow * 2 + 0];
                float v1 = acc[mt][nt][hrow * 2 + 1];
                float2 gg = *reinterpret_cast<const float2*>(n2g + cl);
                float2 bv = *reinterpret_cast<const float2*>(n2b + cl);
                float2 yo;
                yo.x = tf32r((v0 - mean) * inv * gg.x + bv.x);
                yo.y = tf32r((v1 - mean) * inv * gg.y + bv.y);
                int c32 = cl & 31;
                int scol = c32 ^ ((rl & 7) * 4);
                *reinterpret_cast<float2*>(gsm + wn * 4096 + rl * 32 + scol) = yo;
            }
        }
    }

    for (int t = 0; t < 16; t++) {
        if (t + 1 < 16) CP_WAIT(1); else CP_WAIT(0);
        __syncthreads();
        if ((t & 3) == 0) {
            #pragma unroll
            for (int i = 0; i < 4; i++)
                #pragma unroll
                for (int j = 0; j < 4; j++)
                    #pragma unroll
                    for (int q = 0; q < 4; q++) acc[i][j][q] = 0.0f;
        }
        mma_chunk(gsm + (t & 3) * 4096, gsm + 16384 + (t % 3) * 4096, acc, wm, wn, g, cc);
        if (t + 2 < 16) issueW1(t + 2);
        if ((t & 3) == 3) {
            int n0 = (t >> 2) * 128;
            #pragma unroll
            for (int mt = 0; mt < 4; mt++) {
                int r0 = m0 + wm * 64 + mt * 16 + g;
                #pragma unroll
                for (int nt = 0; nt < 4; nt++) {
                    int cb = n0 + wn * 32 + nt * 8 + cc * 2;
                    float2 bb = *reinterpret_cast<const float2*>(b1 + cb);
                    #pragma unroll
                    for (int hrow = 0; hrow < 2; hrow++) {
                        int row = r0 + hrow * 8;
                        float v0 = acc[mt][nt][hrow * 2 + 0] + bb.x;
                        float v1 = acc[mt][nt][hrow * 2 + 1] + bb.y;
                        v0 = tf32r(0.5f * v0 * (1.0f + erff(v0 * 0.70710678118654752f)));
                        v1 = tf32r(0.5f * v1 * (1.0f + erff(v1 * 0.70710678118654752f)));
                        float2 o; o.x = v0; o.y = v1;
                        *reinterpret_cast<float2*>(Chid + (size_t)row * 512 + cb) = o;
                    }
                }
            }
        }
    }
}

// ============ fc2: streaming 3-stage, +bias +residual(window) -> out(scatter)
__global__ void __launch_bounds__(256, 2)
fc2_gemm(const float* __restrict__ A, const float* __restrict__ W,
         const float* __restrict__ bias, const float* __restrict__ res,
         float* __restrict__ C) {
    extern __shared__ float gsm[];
    uint32_t sb = smem_u32(gsm);
    int tid = threadIdx.x;
    int wid = tid >> 5, lane = tid & 31;
    int g = lane >> 2, cc = lane & 3;
    int m0 = blockIdx.x * 128;
    int wm = wid & 1, wn = wid >> 1;

    float acc[4][4][4];
    #pragma unroll
    for (int i = 0; i < 4; i++)
        #pragma unroll
        for (int j = 0; j < 4; j++)
            #pragma unroll
            for (int t = 0; t < 4; t++) acc[i][j][t] = 0.0f;

    int r_ld = tid >> 3, c4_ld = tid & 7;
    uint32_t soff_base = ((uint32_t)r_ld * 32 + (((uint32_t)c4_ld * 4) ^ ((r_ld & 7) * 4))) * 4;

    auto issue = [&](int kc) {
        int k0 = kc * 32;
        uint32_t st = sb + (uint32_t)(kc % 3) * 32768u;
        #pragma unroll
        for (int i = 0; i < 4; i++) {
            int r = r_ld + i * 32;
            uint32_t soff = soff_base + (uint32_t)i * 4096;
            CP16(st + soff, A + (size_t)(m0 + r) * 512 + k0 + c4_ld * 4);
            CP16(st + 16384u + soff, W + (size_t)r * 512 + k0 + c4_ld * 4);
        }
        CP_COMMIT();
    };

    issue(0);
    issue(1);
    for (int kc = 0; kc < 16; kc++) {
        if (kc + 1 < 16) CP_WAIT(1); else CP_WAIT(0);
        __syncthreads();
        const float* st = gsm + (kc % 3) * 8192;
        mma_chunk(st, st + 4096, acc, wm, wn, g, cc);
        if (kc + 2 < 16) issue(kc + 2);
    }

    #pragma unroll
    for (int mt = 0; mt < 4; mt++) {
        #pragma unroll
        for (int hrow = 0; hrow < 2; hrow++) {
            int rl = wm * 64 + mt * 16 + g + hrow * 8;
            int rsp = win_to_spatial(m0 + rl);
            #pragma unroll
            for (int nt = 0; nt < 4; nt++) {
                int cb = wn * 32 + nt * 8 + cc * 2;
                float2 bb = *reinterpret_cast<const float2*>(bias + cb);
                float2 r2 = *reinterpret_cast<const float2*>(res + (size_t)(m0 + rl) * CD + cb);
                float2 o;
                o.x = acc[mt][nt][hrow * 2 + 0] + bb.x + r2.x;
                o.y = acc[mt][nt][hrow * 2 + 1] + bb.y + r2.y;
                *reinterpret_cast<float2*>(C + (size_t)rsp * CD + cb) = o;
            }
        }
    }
}

// ---------------- flash-style register attention (cp.async prologue) --------
__global__ void __launch_bounds__(224, 3)
attn_flash(const float* __restrict__ mask) {
    __shared__ float Qs[112 * 32];
    __shared__ float Ks[104 * 32];
    __shared__ float Vs[104 * 32];
    int win = blockIdx.x, h = blockIdx.y;
    int tid = threadIdx.x, wid = tid >> 5, lane = tid & 31;
    int g = lane >> 2, cc = lane & 3;

    // zero pad rows
    for (int i = tid; i < 14 * 32; i += 224) Qs[98 * 32 + i] = 0.0f;
    if (tid < 192) { Ks[98 * 32 + tid] = 0.0f; Vs[98 * 32 + tid] = 0.0f; }

    // cp.async prologue: raw fp32 copies (mma truncates to tf32; scale folded later)
    {
        uint32_t qb_ = smem_u32(Qs), kb_ = smem_u32(Ks), vb_ = smem_u32(Vs);
        const float* base = g_qkv + (size_t)win * NL * 384 + h * 32;
        for (int e = tid; e < 98 * 24; e += 224) {
            int tok = e / 24, p = e - tok * 24;
            int which = p >> 3, c4 = p & 7;
            uint32_t sbuf = (which == 0) ? qb_ : (which == 1) ? kb_ : vb_;
            uint32_t dst = sbuf + ((uint32_t)tok * 32 + (((uint32_t)c4 * 4) ^ ((tok & 7) * 4))) * 4;
            CP16(dst, base + (size_t)tok * 384 + which * 128 + c4 * 4);
        }
        CP_COMMIT();
        CP_WAIT(0);
    }
    __syncthreads();

    int m0 = wid * 16;
    int r0 = m0 + g, r1 = m0 + g + 8;
    int sw = g * 4;

    uint32_t aq[4][4];
    #pragma unroll
    for (int kc = 0; kc < 4; kc++) {
        int col0 = (kc * 8 + cc) ^ sw;
        int col1 = (kc * 8 + cc + 4) ^ sw;
        aq[kc][0] = __float_as_uint(Qs[r0 * 32 + col0]);
        aq[kc][1] = __float_as_uint(Qs[r1 * 32 + col0]);
        aq[kc][2] = __float_as_uint(Qs[r0 * 32 + col1]);
        aq[kc][3] = __float_as_uint(Qs[r1 * 32 + col1]);
    }

    float sacc[13][4];
    #pragma unroll
    for (int nt = 0; nt < 13; nt++) {
        float s[4] = {0.f, 0.f, 0.f, 0.f};
        int nr = nt * 8 + g;
        #pragma unroll
        for (int kc = 0; kc < 4; kc++) {
            int col0 = (kc * 8 + cc) ^ sw;
            int col1 = (kc * 8 + cc + 4) ^ sw;
            uint32_t b0 = __float_as_uint(Ks[nr * 32 + col0]);
            uint32_t b1 = __float_as_uint(Ks[nr * 32 + col1]);
            mma_tf32(s, aq[kc][0], aq[kc][1], aq[kc][2], aq[kc][3], b0, b1);
        }
        sacc[nt][0] = s[0]; sacc[nt][1] = s[1]; sacc[nt][2] = s[2]; sacc[nt][3] = s[3];
    }

    // scale (folded 1/sqrt(32)) + bias + mask
    {
        const float sc = 0.17677669529663689f;
        const float* bm = g_bias + (size_t)h * (NL * NL);
        const float* mk = mask + (size_t)(win & 255) * (NL * NL);
        int rc0 = (r0 < 98 ? r0 : 97) * 98;
        int rc1 = (r1 < 98 ? r1 : 97) * 98;
        #pragma unroll
        for (int nt = 0; nt < 13; nt++) {
            int col = nt * 8 + 2 * cc;
            if (col < 98) {
                sacc[nt][0] = fmaf(sacc[nt][0], sc, __ldg(bm + rc0 + col) + __ldg(mk + rc0 + col));
                sacc[nt][2] = fmaf(sacc[nt][2], sc, __ldg(bm + rc1 + col) + __ldg(mk + rc1 + col));
            } else { sacc[nt][0] = -1.0e38f; sacc[nt][2] = -1.0e38f; }
            if (col + 1 < 98) {
                sacc[nt][1] = fmaf(sacc[nt][1], sc, __ldg(bm + rc0 + col + 1) + __ldg(mk + rc0 + col + 1));
                sacc[nt][3] = fmaf(sacc[nt][3], sc, __ldg(bm + rc1 + col + 1) + __ldg(mk + rc1 + col + 1));
            } else { sacc[nt][1] = -1.0e38f; sacc[nt][3] = -1.0e38f; }
        }
    }

    float mx0 = -1.0e38f, mx1 = -1.0e38f;
    #pragma unroll
    for (int nt = 0; nt < 13; nt++) {
        mx0 = fmaxf(mx0, fmaxf(sacc[nt][0], sacc[nt][1]));
        mx1 = fmaxf(mx1, fmaxf(sacc[nt][2], sacc[nt][3]));
    }
    mx0 = fmaxf(mx0, __shfl_xor_sync(0xffffffffu, mx0, 1));
    mx0 = fmaxf(mx0, __shfl_xor_sync(0xffffffffu, mx0, 2));
    mx1 = fmaxf(mx1, __shfl_xor_sync(0xffffffffu, mx1, 1));
    mx1 = fmaxf(mx1, __shfl_xor_sync(0xffffffffu, mx1, 2));
    float sm0 = 0.f, sm1 = 0.f;
    #pragma unroll
    for (int nt = 0; nt < 13; nt++) {
        sacc[nt][0] = __expf(sacc[nt][0] - mx0);
        sacc[nt][1] = __expf(sacc[nt][1] - mx0);
        sacc[nt][2] = __expf(sacc[nt][2] - mx1);
        sacc[nt][3] = __expf(sacc[nt][3] - mx1);
        sm0 += sacc[nt][0] + sacc[nt][1];
        sm1 += sacc[nt][2] + sacc[nt][3];
    }
    sm0 += __shfl_xor_sync(0xffffffffu, sm0, 1);
    sm0 += __shfl_xor_sync(0xffffffffu, sm0, 2);
    sm1 += __shfl_xor_sync(0xffffffffu, sm1, 1);
    sm1 += __shfl_xor_sync(0xffffffffu, sm1, 2);
    float iv0 = 1.0f / sm0, iv1 = 1.0f / sm1;
    #pragma unroll
    for (int nt = 0; nt < 13; nt++) {
        sacc[nt][0] *= iv0;
        sacc[nt][1] *= iv0;
        sacc[nt][2] *= iv1;
        sacc[nt][3] *= iv1;
    }

    float oacc[4][4];
    #pragma unroll
    for (int vt = 0; vt < 4; vt++)
        #pragma unroll
        for (int t = 0; t < 4; t++) oacc[vt][t] = 0.0f;
    int qb = lane & ~3;
    int src0 = qb + (cc >> 1);
    bool odd = (cc & 1);
    #pragma unroll
    for (int kc = 0; kc < 13; kc++) {
        float p0 = sacc[kc][0], p1 = sacc[kc][1], p2 = sacc[kc][2], p3 = sacc[kc][3];
        float t0 = __shfl_sync(0xffffffffu, p0, src0);
        float t1 = __shfl_sync(0xffffffffu, p1, src0);
        float u0 = __shfl_sync(0xffffffffu, p0, src0 + 2);
        float u1 = __shfl_sync(0xffffffffu, p1, src0 + 2);
        float t2 = __shfl_sync(0xffffffffu, p2, src0);
        float t3 = __shfl_sync(0xffffffffu, p3, src0);
        float u2 = __shfl_sync(0xffffffffu, p2, src0 + 2);
        float u3 = __shfl_sync(0xffffffffu, p3, src0 + 2);
        uint32_t a0 = __float_as_uint(odd ? t1 : t0);
        uint32_t a2 = __float_as_uint(odd ? u1 : u0);
        uint32_t a1 = __float_as_uint(odd ? t3 : t2);
        uint32_t a3 = __float_as_uint(odd ? u3 : u2);
        int k0 = kc * 8;
        #pragma unroll
        for (int vt = 0; vt < 4; vt++) {
            uint32_t b0 = __float_as_uint(Vs[(k0 + cc) * 32     + ((vt * 8 + g) ^ (cc * 4))]);
            uint32_t b1 = __float_as_uint(Vs[(k0 + cc + 4) * 32 + ((vt * 8 + g) ^ (cc * 4 + 16))]);
            mma_tf32(oacc[vt], a0, a1, a2, a3, b0, b1);
        }
    }

    float* ob = g_attn + (size_t)win * NL * CD + h * 32;
    #pragma unroll
    for (int vt = 0; vt < 4; vt++) {
        int cb = vt * 8 + 2 * cc;
        if (r0 < NL) {
            float2 o; o.x = tf32r(oacc[vt][0]); o.y = tf32r(oacc[vt][1]);
            *reinterpret_cast<float2*>(ob + (size_t)r0 * CD + cb) = o;
        }
        if (r1 < NL) {
            float2 o; o.x = tf32r(oacc[vt][2]); o.y = tf32r(oacc[vt][3]);
            *reinterpret_cast<float2*>(ob + (size_t)r1 * CD + cb) = o;
        }
    }
}

// ---------------- launch ----------------
extern "C" void kernel_launch(void* const* d_in, const int* in_sizes, int n_in,
                              void* d_out, int out_size) {
    const float* x     = (const float*)d_in[0];
    const float* mask  = (const float*)d_in[1];
    const float* n1g   = (const float*)d_in[2];
    const float* n1b   = (const float*)d_in[3];
    const float* qkvw  = (const float*)d_in[4];
    const float* qkvb  = (const float*)d_in[5];
    const float* relb  = (const float*)d_in[6];
    const float* projw = (const float*)d_in[7];
    const float* projb = (const float*)d_in[8];
    const float* n2g   = (const float*)d_in[9];
    const float* n2b   = (const float*)d_in[10];
    const float* fc1w  = (const float*)d_in[11];
    const float* fc1b  = (const float*)d_in[12];
    const float* fc2w  = (const float*)d_in[13];
    const float* fc2b  = (const float*)d_in[14];
    float* out = (float*)d_out;

    void *p_qkv, *p_attn, *p_x2, *p_hid, *p_w;
    cudaGetSymbolAddress(&p_qkv,  g_qkv);
    cudaGetSymbolAddress(&p_attn, g_attn);
    cudaGetSymbolAddress(&p_x2,   g_x2);
    cudaGetSymbolAddress(&p_hid,  g_hid);
    cudaGetSymbolAddress(&p_w,    g_wcvt);
    float* wc = (float*)p_w;

    cudaFuncSetAttribute(qkv_ln_gemm, cudaFuncAttributeMaxDynamicSharedMemorySize, SMEM_AR3);
    cudaFuncSetAttribute(proj_fc1,    cudaFuncAttributeMaxDynamicSharedMemorySize, SMEM_PF1);
    cudaFuncSetAttribute(fc2_gemm,    cudaFuncAttributeMaxDynamicSharedMemorySize, SMEM_3S);

    prep_kernel<<<(W_TOT + NHEAD * NL * NL + 255) / 256, 256>>>(qkvw, projw, fc1w, fc2w, relb);

    qkv_ln_gemm<<<TOKENS / 128, 256, SMEM_AR3>>>(
        x, n1g, n1b, wc + W_QKV, qkvb, (float*)p_qkv);
    attn_flash<<<dim3(NWIN, NHEAD), 224>>>(mask);
    proj_fc1<<<TOKENS / 128, 256, SMEM_PF1>>>(
        (const float*)p_attn, wc + W_PROJ, projb, x, n2g, n2b,
        wc + W_FC1, fc1b, (float*)p_hid);
    fc2_gemm<<<TOKENS / 128, 256, SMEM_3S>>>(
        (const float*)p_hid, wc + W_FC2, fc2b, (const float*)p_x2, out);
}